// round 3
// baseline (speedup 1.0000x reference)
#include <cuda_runtime.h>
#include <cstdint>
#include <math.h>

#define NTOK 32768
#define CDIM 1024
#define NHEAD 16
#define HD 64

// ---------------- scratch (static device allocations are allowed) ----------
__device__ float g_qkv[NTOK * 3 * CDIM];   // 402 MB: qkv, q/k normed+roped in place
__device__ float g_hbuf[NTOK * CDIM];      // 134 MB: attention output (token order)

// ---------------- tf32 helpers --------------------------------------------
__device__ __forceinline__ float f2tf(float x) {
    uint32_t u;
    asm("cvt.rna.tf32.f32 %0, %1;" : "=r"(u) : "f"(x));
    return __uint_as_float(u);
}

__device__ __forceinline__ void mma_tf32(float* d, const uint32_t* a, const uint32_t* b) {
    asm volatile(
        "mma.sync.aligned.m16n8k8.row.col.f32.tf32.tf32.f32 "
        "{%0,%1,%2,%3}, {%4,%5,%6,%7}, {%8,%9}, {%0,%1,%2,%3};\n"
        : "+f"(d[0]), "+f"(d[1]), "+f"(d[2]), "+f"(d[3])
        : "r"(a[0]), "r"(a[1]), "r"(a[2]), "r"(a[3]), "r"(b[0]), "r"(b[1]));
}

// ---------------- GEMM: C[M,N] = A[M,K]*B[K,N] + bias[N] (tf32 MMA) --------
// Block tile 128x128, K-tile 32, 256 threads = 8 warps (2x4), warp tile 64x32.
#define GBK 32
#define GPAD 136
#define GTILE (GBK * GPAD)          // 4352 floats per buffer
#define GEMM_SMEM (4 * GTILE * 4)   // 69632 bytes (A0,A1,B0,B1)

__global__ __launch_bounds__(256, 1)
void gemm_tf32_kernel(const float* __restrict__ A, const float* __restrict__ B,
                      const float* __restrict__ bias, float* __restrict__ Cmat,
                      int M, int N, int K)
{
    extern __shared__ float sgm[];
    const int tid  = threadIdx.x;
    const int lane = tid & 31, warp = tid >> 5;
    const int g    = lane >> 2, tg = lane & 3;
    const int wr   = warp >> 2, wc = warp & 3;
    const int rowBase = blockIdx.y * 128;
    const int colBase = blockIdx.x * 128;

    float acc[4][4][4];
#pragma unroll
    for (int mi = 0; mi < 4; mi++)
#pragma unroll
        for (int ni = 0; ni < 4; ni++)
#pragma unroll
            for (int q = 0; q < 4; q++) acc[mi][ni][q] = 0.f;

    const int NT = K / GBK;
    float4 aReg[4], bReg[4];

    // prefetch tile 0
#pragma unroll
    for (int i = 0; i < 4; i++) {
        int slot = tid + i * 256;
        int r = slot >> 3, c4 = (slot & 7) << 2;
        aReg[i] = *(const float4*)(A + (size_t)(rowBase + r) * K + c4);
        int kb = slot >> 5, cc = (slot & 31) << 2;
        bReg[i] = *(const float4*)(B + (size_t)kb * N + colBase + cc);
    }

    int buf = 0;
    for (int kt = 0; kt < NT; ++kt) {
        float* As = sgm + buf * GTILE;
        float* Bs = sgm + 2 * GTILE + buf * GTILE;

        // regs -> smem (A transposed to [k][row], both converted to tf32)
#pragma unroll
        for (int i = 0; i < 4; i++) {
            int slot = tid + i * 256;
            int r = slot >> 3, k0 = (slot & 7) << 2;
            As[(k0 + 0) * GPAD + r] = f2tf(aReg[i].x);
            As[(k0 + 1) * GPAD + r] = f2tf(aReg[i].y);
            As[(k0 + 2) * GPAD + r] = f2tf(aReg[i].z);
            As[(k0 + 3) * GPAD + r] = f2tf(aReg[i].w);
            int kb = slot >> 5, cc = (slot & 31) << 2;
            float4 bv;
            bv.x = f2tf(bReg[i].x); bv.y = f2tf(bReg[i].y);
            bv.z = f2tf(bReg[i].z); bv.w = f2tf(bReg[i].w);
            *(float4*)(Bs + kb * GPAD + cc) = bv;
        }
        __syncthreads();

        if (kt + 1 < NT) {
#pragma unroll
            for (int i = 0; i < 4; i++) {
                int slot = tid + i * 256;
                int r = slot >> 3, c4 = (slot & 7) << 2;
                aReg[i] = *(const float4*)(A + (size_t)(rowBase + r) * K + (kt + 1) * GBK + c4);
                int kb = slot >> 5, cc = (slot & 31) << 2;
                bReg[i] = *(const float4*)(B + (size_t)((kt + 1) * GBK + kb) * N + colBase + cc);
            }
        }

#pragma unroll
        for (int ks = 0; ks < 4; ++ks) {
            const int k0 = ks * 8;
            uint32_t af[4][4], bf[4][2];
#pragma unroll
            for (int mi = 0; mi < 4; mi++) {
                int r = wr * 64 + mi * 16 + g;
                af[mi][0] = __float_as_uint(As[(k0 + tg) * GPAD + r]);
                af[mi][1] = __float_as_uint(As[(k0 + tg) * GPAD + r + 8]);
                af[mi][2] = __float_as_uint(As[(k0 + tg + 4) * GPAD + r]);
                af[mi][3] = __float_as_uint(As[(k0 + tg + 4) * GPAD + r + 8]);
            }
#pragma unroll
            for (int ni = 0; ni < 4; ni++) {
                int c = wc * 32 + ni * 8 + g;
                bf[ni][0] = __float_as_uint(Bs[(k0 + tg) * GPAD + c]);
                bf[ni][1] = __float_as_uint(Bs[(k0 + tg + 4) * GPAD + c]);
            }
#pragma unroll
            for (int mi = 0; mi < 4; mi++)
#pragma unroll
                for (int ni = 0; ni < 4; ni++)
                    mma_tf32(acc[mi][ni], af[mi], bf[ni]);
        }
        buf ^= 1;
    }

    // epilogue: + bias, store
#pragma unroll
    for (int mi = 0; mi < 4; mi++) {
        int r0 = rowBase + wr * 64 + mi * 16 + g;
#pragma unroll
        for (int ni = 0; ni < 4; ni++) {
            int c0 = colBase + wc * 32 + ni * 8 + tg * 2;
            float b0 = __ldg(bias + c0), b1 = __ldg(bias + c0 + 1);
            float2 v;
            v.x = acc[mi][ni][0] + b0; v.y = acc[mi][ni][1] + b1;
            *(float2*)(Cmat + (size_t)r0 * N + c0) = v;
            v.x = acc[mi][ni][2] + b0; v.y = acc[mi][ni][3] + b1;
            *(float2*)(Cmat + (size_t)(r0 + 8) * N + c0) = v;
        }
    }
}

// ---------------- RMSNorm + RoPE, in place on q,k --------------------------
// one warp per (token, head); lane j owns the pair (2j, 2j+1)
__global__ __launch_bounds__(256)
void normrope_kernel(float* __restrict__ qkv, const int* __restrict__ coords,
                     const float* __restrict__ gq, const float* __restrict__ gk)
{
    const int wid  = blockIdx.x * 8 + (threadIdx.x >> 5);
    const int lane = threadIdx.x & 31;
    const int n = wid >> 4;
    const int h = wid & 15;

    const int j = lane;
    float c = 1.f, s = 0.f;
    if (j < 30) {
        int axis = (j >= 20) ? 2 : ((j >= 10) ? 1 : 0);
        int f = j - axis * 10;
        // freq = 10000^(-f/10) = 2^(f * -0.1*log2(10000))
        float freq = exp2f((float)f * -1.32877123795494493f);
        float phase = (float)__ldg(coords + n * 3 + axis) * freq;
        sincosf(phase, &s, &c);
    }

    float* qp = qkv + (size_t)n * 3072 + h * 64;

#pragma unroll
    for (int pass = 0; pass < 2; ++pass) {
        float* p = qp + pass * 1024;            // q then k
        const float* gamma = (pass == 0 ? gq : gk) + h * 64;
        float2 t = *(float2*)(p + 2 * j);
        float ss = t.x * t.x + t.y * t.y;
#pragma unroll
        for (int o = 16; o > 0; o >>= 1) ss += __shfl_xor_sync(0xffffffffu, ss, o);
        float inv = 8.0f / fmaxf(sqrtf(ss), 1e-12f);   // * sqrt(D)/||t||
        float v0 = t.x * inv * __ldg(gamma + 2 * j);
        float v1 = t.y * inv * __ldg(gamma + 2 * j + 1);
        float2 o2;
        o2.x = v0 * c - v1 * s;
        o2.y = v0 * s + v1 * c;
        *(float2*)(p + 2 * j) = o2;
    }
}

// ---------------- windowed attention ---------------------------------------
// block = (window, head, 128-query chunk); 256 threads; exact softmax (scores
// are bounded |s|<=8 since ||q||=||k||=8 and scale=1/8), so no running max.
#define AQOFF 0
#define AKOFF 8320
#define AVOFF 16640
#define ASOFF 24960
#define ALOFF 41472
#define ATTN_SMEM (41600 * 4)

__device__ __forceinline__ int win_token(int w, int p) {
    int wx = w >> 4, wy = (w >> 2) & 3, wz = w & 3;
    int px = p >> 6, py = (p >> 3) & 7, pz = p & 7;
    return ((((wx << 3) + px) << 10) | (((wy << 3) + py) << 5) | ((wz << 3) + pz));
}

__global__ __launch_bounds__(256, 1)
void attn_kernel(const float* __restrict__ qkv, float* __restrict__ hout)
{
    extern __shared__ float sm[];
    const int tid  = threadIdx.x;
    const int b    = blockIdx.x;
    const int qc   = b & 3;
    const int head = (b >> 2) & 15;
    const int w    = b >> 6;

    // load Q chunk (pre-scaled by 1/sqrt(D))
#pragma unroll
    for (int i = 0; i < 8; i++) {
        int slot = tid + i * 256;
        int r = slot >> 4, d4 = (slot & 15) << 2;
        int n = win_token(w, qc * 128 + r);
        float4 v = *(const float4*)(qkv + (size_t)n * 3072 + head * 64 + d4);
        float* dst = sm + AQOFF + r * 65 + d4;
        dst[0] = v.x * 0.125f; dst[1] = v.y * 0.125f;
        dst[2] = v.z * 0.125f; dst[3] = v.w * 0.125f;
    }
    if (tid < 128) sm[ALOFF + tid] = 0.f;

    float acc[4][8];
#pragma unroll
    for (int i = 0; i < 4; i++)
#pragma unroll
        for (int jj = 0; jj < 8; jj++) acc[i][jj] = 0.f;

    const int ty = tid >> 4, tx = tid & 15;          // S tile: 8x8 per thread
    const int pr = (tid >> 3) << 2;                  // PV tile: 4 rows
    const int pc = (tid & 7) << 3;                   // PV tile: 8 cols

    for (int kt = 0; kt < 4; ++kt) {
        __syncthreads();
        // load K, V tiles (gather by window permutation)
#pragma unroll
        for (int i = 0; i < 8; i++) {
            int slot = tid + i * 256;
            int r = slot >> 4, d4 = (slot & 15) << 2;
            int n = win_token(w, kt * 128 + r);
            const float* base = qkv + (size_t)n * 3072 + head * 64 + d4;
            float4 kv = *(const float4*)(base + 1024);
            float4 vv = *(const float4*)(base + 2048);
            float* kd = sm + AKOFF + r * 65 + d4;
            kd[0] = kv.x; kd[1] = kv.y; kd[2] = kv.z; kd[3] = kv.w;
            float* vd = sm + AVOFF + r * 65 + d4;
            vd[0] = vv.x; vd[1] = vv.y; vd[2] = vv.z; vd[3] = vv.w;
        }
        __syncthreads();

        // S = Q K^T  (128x128), 8x8 register tile / thread
        {
            float sr[8][8];
#pragma unroll
            for (int i = 0; i < 8; i++)
#pragma unroll
                for (int jj = 0; jj < 8; jj++) sr[i][jj] = 0.f;
#pragma unroll 8
            for (int d = 0; d < 64; ++d) {
                float qv[8], kv[8];
#pragma unroll
                for (int i = 0; i < 8; i++) qv[i] = sm[AQOFF + (ty * 8 + i) * 65 + d];
#pragma unroll
                for (int jj = 0; jj < 8; jj++) kv[jj] = sm[AKOFF + (tx * 8 + jj) * 65 + d];
#pragma unroll
                for (int i = 0; i < 8; i++)
#pragma unroll
                    for (int jj = 0; jj < 8; jj++) sr[i][jj] += qv[i] * kv[jj];
            }
#pragma unroll
            for (int i = 0; i < 8; i++)
#pragma unroll
                for (int jj = 0; jj < 8; jj++)
                    sm[ASOFF + (ty * 8 + i) * 129 + tx * 8 + jj] = sr[i][jj];
        }
        __syncthreads();

        // exp + row sums (2 threads per row, halves combined via shfl)
        {
            int r = tid >> 1;
            int hh = (tid & 1) << 6;
            float* srow = sm + ASOFF + r * 129 + hh;
            float ssum = 0.f;
#pragma unroll 8
            for (int k2 = 0; k2 < 64; k2++) {
                float p = __expf(srow[k2]);
                srow[k2] = p;
                ssum += p;
            }
            ssum += __shfl_xor_sync(0xffffffffu, ssum, 1);
            if ((tid & 1) == 0) sm[ALOFF + r] += ssum;
        }
        __syncthreads();

        // acc += P * V   (4x8 register tile / thread)
#pragma unroll 4
        for (int kk = 0; kk < 128; ++kk) {
            float pv[4], vv[8];
#pragma unroll
            for (int i = 0; i < 4; i++) pv[i] = sm[ASOFF + (pr + i) * 129 + kk];
#pragma unroll
            for (int jj = 0; jj < 8; jj++) vv[jj] = sm[AVOFF + kk * 65 + pc + jj];
#pragma unroll
            for (int i = 0; i < 4; i++)
#pragma unroll
                for (int jj = 0; jj < 8; jj++) acc[i][jj] += pv[i] * vv[jj];
        }
    }

    // normalize and write h in token order
#pragma unroll
    for (int i = 0; i < 4; i++) {
        int rr = pr + i;
        float linv = 1.0f / sm[ALOFF + rr];
        int n = win_token(w, qc * 128 + rr);
        float* op = hout + (size_t)n * 1024 + head * 64 + pc;
        float4 o1, o2;
        o1.x = acc[i][0] * linv; o1.y = acc[i][1] * linv;
        o1.z = acc[i][2] * linv; o1.w = acc[i][3] * linv;
        o2.x = acc[i][4] * linv; o2.y = acc[i][5] * linv;
        o2.z = acc[i][6] * linv; o2.w = acc[i][7] * linv;
        *(float4*)op = o1;
        *(float4*)(op + 4) = o2;
    }
}

// ---------------- launch ----------------------------------------------------
extern "C" void kernel_launch(void* const* d_in, const int* in_sizes, int n_in,
                              void* d_out, int out_size)
{
    const float* x     = (const float*)d_in[0];
    const int*   coords = (const int*)d_in[1];
    const float* Wqkv  = (const float*)d_in[2];
    const float* bqkv  = (const float*)d_in[3];
    const float* gq    = (const float*)d_in[4];
    const float* gk    = (const float*)d_in[5];
    const float* Wout  = (const float*)d_in[6];
    const float* bout  = (const float*)d_in[7];
    float* out = (float*)d_out;

    cudaFuncSetAttribute(gemm_tf32_kernel, cudaFuncAttributeMaxDynamicSharedMemorySize, GEMM_SMEM);
    cudaFuncSetAttribute(attn_kernel, cudaFuncAttributeMaxDynamicSharedMemorySize, ATTN_SMEM);

    float *qkv_ptr = nullptr, *h_ptr = nullptr;
    cudaGetSymbolAddress((void**)&qkv_ptr, g_qkv);
    cudaGetSymbolAddress((void**)&h_ptr, g_hbuf);

    // 1) qkv = x @ Wqkv + bqkv
    gemm_tf32_kernel<<<dim3(3072 / 128, NTOK / 128), 256, GEMM_SMEM>>>(
        x, Wqkv, bqkv, qkv_ptr, NTOK, 3072, CDIM);

    // 2) in-place RMSNorm + RoPE on q,k
    normrope_kernel<<<(NTOK * NHEAD) / 8, 256>>>(qkv_ptr, coords, gq, gk);

    // 3) windowed attention -> h (token order)
    attn_kernel<<<64 * 16 * 4, 256, ATTN_SMEM>>>(qkv_ptr, h_ptr);

    // 4) out = h @ Wout + bout
    gemm_tf32_kernel<<<dim3(1024 / 128, NTOK / 128), 256, GEMM_SMEM>>>(
        h_ptr, Wout, bout, out, NTOK, 1024, CDIM);
}

// round 4
// speedup vs baseline: 1.4653x; 1.4653x over previous
#include <cuda_runtime.h>
#include <cstdint>
#include <math.h>

#define NTOK 32768
#define CDIM 1024
#define NHEAD 16
#define HD 64

// ---------------- scratch ---------------------------------------------------
__device__ float g_qkv[NTOK * 3 * CDIM];
__device__ float g_hbuf[NTOK * CDIM];

// ---------------- helpers ---------------------------------------------------
__device__ __forceinline__ uint32_t f2tfu(float x) {
    uint32_t u;
    asm("cvt.rna.tf32.f32 %0, %1;" : "=r"(u) : "f"(x));
    return u;
}

__device__ __forceinline__ void mma_tf32(float* d, const uint32_t* a, const uint32_t* b) {
    asm volatile(
        "mma.sync.aligned.m16n8k8.row.col.f32.tf32.tf32.f32 "
        "{%0,%1,%2,%3}, {%4,%5,%6,%7}, {%8,%9}, {%0,%1,%2,%3};\n"
        : "+f"(d[0]), "+f"(d[1]), "+f"(d[2]), "+f"(d[3])
        : "r"(a[0]), "r"(a[1]), "r"(a[2]), "r"(a[3]), "r"(b[0]), "r"(b[1]));
}

__device__ __forceinline__ void cpasync16(uint32_t dst, const void* src) {
    asm volatile("cp.async.cg.shared.global [%0], [%1], 16;" :: "r"(dst), "l"(src));
}

// packed fp32x2 (FFMA2) — doubles fp32 FMA throughput on Blackwell
typedef unsigned long long ull;
union F2U { float2 f; ull u; };

__device__ __forceinline__ void fma2(ull& d, ull a, ull b) {
    asm("fma.rn.f32x2 %0, %1, %2, %0;" : "+l"(d) : "l"(a), "l"(b));
}
__device__ __forceinline__ ull bcast2(float x) {
    ull r;
    asm("mov.b64 %0, {%1, %1};" : "=l"(r) : "r"(__float_as_uint(x)));
    return r;
}

// ---------------- GEMM: C[M,N] = A[M,K]*B[K,N] + bias[N] (tf32 MMA) --------
// 128x128 tile, K-tile 32, cp.async double-buffer, 2 CTAs/SM.
// As [128][68] row-major raw f32, Bs [32][136] raw f32; cvt->tf32 at frag load.
#define APAD 68
#define BPAD 136
#define A_TILE (128 * APAD)     // 8704 floats
#define B_TILE (32 * BPAD)      // 4352 floats
#define GEMM_SMEM ((2 * A_TILE + 2 * B_TILE) * 4)   // 104448 bytes

__global__ __launch_bounds__(256, 2)
void gemm_tf32_kernel(const float* __restrict__ A, const float* __restrict__ B,
                      const float* __restrict__ bias, float* __restrict__ Cmat,
                      int M, int N, int K)
{
    extern __shared__ float sgm[];
    const uint32_t sbase = (uint32_t)__cvta_generic_to_shared(sgm);
    const int tid  = threadIdx.x;
    const int lane = tid & 31, warp = tid >> 5;
    const int g    = lane >> 2, tg = lane & 3;
    const int wr   = warp >> 2, wc = warp & 3;
    const int rowBase = blockIdx.y * 128;
    const int colBase = blockIdx.x * 128;
    const int NT = K >> 5;

    float acc[4][4][4];
#pragma unroll
    for (int mi = 0; mi < 4; mi++)
#pragma unroll
        for (int ni = 0; ni < 4; ni++)
#pragma unroll
            for (int q = 0; q < 4; q++) acc[mi][ni][q] = 0.f;

    // precomputed per-thread copy indices
    const int arow = tid >> 3, ac4 = (tid & 7) << 2;       // +32 rows per i
    const int bkb  = tid >> 5, bcc = (tid & 31) << 2;      // +8 k-rows per i

    auto issue = [&](int kt, int buf) {
        uint32_t sA = sbase + (uint32_t)(buf * A_TILE) * 4u;
        uint32_t sB = sbase + (uint32_t)(2 * A_TILE + buf * B_TILE) * 4u;
#pragma unroll
        for (int i = 0; i < 4; i++) {
            int r = arow + i * 32;
            cpasync16(sA + (uint32_t)(r * APAD + ac4) * 4u,
                      A + (size_t)(rowBase + r) * K + kt * 32 + ac4);
            int kb = bkb + i * 8;
            cpasync16(sB + (uint32_t)(kb * BPAD + bcc) * 4u,
                      B + (size_t)(kt * 32 + kb) * N + colBase + bcc);
        }
        asm volatile("cp.async.commit_group;");
    };

    issue(0, 0);
    issue(1, 1);

    for (int kt = 0; kt < NT; ++kt) {
        if (kt < NT - 1) asm volatile("cp.async.wait_group 1;");
        else             asm volatile("cp.async.wait_group 0;");
        __syncthreads();

        const float* As = sgm + (kt & 1) * A_TILE;
        const float* Bs = sgm + 2 * A_TILE + (kt & 1) * B_TILE;

#pragma unroll
        for (int ks = 0; ks < 4; ++ks) {
            const int k0 = ks * 8;
            uint32_t af[4][4], bf[4][2];
#pragma unroll
            for (int mi = 0; mi < 4; mi++) {
                const float* ap = As + (wr * 64 + mi * 16 + g) * APAD + k0 + tg;
                af[mi][0] = f2tfu(ap[0]);
                af[mi][1] = f2tfu(ap[8 * APAD]);
                af[mi][2] = f2tfu(ap[4]);
                af[mi][3] = f2tfu(ap[8 * APAD + 4]);
            }
#pragma unroll
            for (int ni = 0; ni < 4; ni++) {
                const float* bp = Bs + (k0 + tg) * BPAD + wc * 32 + ni * 8 + g;
                bf[ni][0] = f2tfu(bp[0]);
                bf[ni][1] = f2tfu(bp[4 * BPAD]);
            }
#pragma unroll
            for (int mi = 0; mi < 4; mi++)
#pragma unroll
                for (int ni = 0; ni < 4; ni++)
                    mma_tf32(acc[mi][ni], af[mi], bf[ni]);
        }
        __syncthreads();
        if (kt + 2 < NT) issue(kt + 2, kt & 1);
    }

    // epilogue
#pragma unroll
    for (int mi = 0; mi < 4; mi++) {
        int r0 = rowBase + wr * 64 + mi * 16 + g;
#pragma unroll
        for (int ni = 0; ni < 4; ni++) {
            int c0 = colBase + wc * 32 + ni * 8 + tg * 2;
            float b0 = __ldg(bias + c0), b1 = __ldg(bias + c0 + 1);
            float2 v;
            v.x = acc[mi][ni][0] + b0; v.y = acc[mi][ni][1] + b1;
            *(float2*)(Cmat + (size_t)r0 * N + c0) = v;
            v.x = acc[mi][ni][2] + b0; v.y = acc[mi][ni][3] + b1;
            *(float2*)(Cmat + (size_t)(r0 + 8) * N + c0) = v;
        }
    }
}

// ---------------- RMSNorm + RoPE, in place on q,k --------------------------
__global__ __launch_bounds__(256)
void normrope_kernel(float* __restrict__ qkv, const int* __restrict__ coords,
                     const float* __restrict__ gq, const float* __restrict__ gk)
{
    const int wid  = blockIdx.x * 8 + (threadIdx.x >> 5);
    const int lane = threadIdx.x & 31;
    const int n = wid >> 4;
    const int h = wid & 15;

    const int j = lane;
    float c = 1.f, s = 0.f;
    if (j < 30) {
        int axis = (j >= 20) ? 2 : ((j >= 10) ? 1 : 0);
        int f = j - axis * 10;
        float freq = exp2f((float)f * -1.32877123795494493f);
        float phase = (float)__ldg(coords + n * 3 + axis) * freq;
        sincosf(phase, &s, &c);
    }

    float* qp = qkv + (size_t)n * 3072 + h * 64;

#pragma unroll
    for (int pass = 0; pass < 2; ++pass) {
        float* p = qp + pass * 1024;
        const float* gamma = (pass == 0 ? gq : gk) + h * 64;
        float2 t = *(float2*)(p + 2 * j);
        float ss = t.x * t.x + t.y * t.y;
#pragma unroll
        for (int o = 16; o > 0; o >>= 1) ss += __shfl_xor_sync(0xffffffffu, ss, o);
        float inv = 8.0f / fmaxf(sqrtf(ss), 1e-12f);
        float v0 = t.x * inv * __ldg(gamma + 2 * j);
        float v1 = t.y * inv * __ldg(gamma + 2 * j + 1);
        float2 o2;
        o2.x = v0 * c - v1 * s;
        o2.y = v0 * s + v1 * c;
        *(float2*)(p + 2 * j) = o2;
    }
}

// ---------------- windowed attention (fp32x2 packed FMA) -------------------
// smem (floats): Qt [64][130] (d-major, q-scaled), Kt [64][130] (d-major),
//                Vs [128][68], S [128][130], L [128]
#define QTOFF 0
#define KTOFF 8320
#define VOFF  16640
#define SOFF  25344
#define LOFF  41984
#define ATTN_SMEM (42112 * 4)   // 168448 bytes

__device__ __forceinline__ int win_token(int w, int p) {
    int wx = w >> 4, wy = (w >> 2) & 3, wz = w & 3;
    int px = p >> 6, py = (p >> 3) & 7, pz = p & 7;
    return ((((wx << 3) + px) << 10) | (((wy << 3) + py) << 5) | ((wz << 3) + pz));
}

__global__ __launch_bounds__(256, 1)
void attn_kernel(const float* __restrict__ qkv, float* __restrict__ hout)
{
    extern __shared__ float sm[];
    const int tid  = threadIdx.x;
    const int b    = blockIdx.x;
    const int qc   = b & 3;
    const int head = (b >> 2) & 15;
    const int w    = b >> 6;

    // --- load Q chunk, transposed to [d][q], pre-scaled by 1/8 ---
#pragma unroll
    for (int i = 0; i < 8; i++) {
        int slot = tid + i * 256;
        int r = slot & 127;
        int d4 = (slot >> 7) << 2;
        int n = win_token(w, qc * 128 + r);
        float4 v = *(const float4*)(qkv + (size_t)n * 3072 + head * 64 + d4);
        float* dst = sm + QTOFF;
        dst[(d4 + 0) * 130 + r] = v.x * 0.125f;
        dst[(d4 + 1) * 130 + r] = v.y * 0.125f;
        dst[(d4 + 2) * 130 + r] = v.z * 0.125f;
        dst[(d4 + 3) * 130 + r] = v.w * 0.125f;
    }
    if (tid < 128) sm[LOFF + tid] = 0.f;

    // PV accumulators: rows pr..pr+3, cols {pc4..pc4+3, pc4+32..pc4+35}
    const int pr  = (tid >> 3) << 2;
    const int pc4 = (tid & 7) << 2;
    ull oacc[4][4];
#pragma unroll
    for (int i = 0; i < 4; i++)
#pragma unroll
        for (int jj = 0; jj < 4; jj++) oacc[i][jj] = 0ull;

    // S-tile mapping: q rows ty*8..+7 (pairs), keys tx + 16*jj
    const int ty = tid >> 4, tx = tid & 15;

    for (int kt = 0; kt < 4; ++kt) {
        __syncthreads();
        // --- load K (transposed [d][key]) and V ([key][d]) ---
#pragma unroll
        for (int i = 0; i < 8; i++) {
            int slot = tid + i * 256;
            int r = slot & 127;
            int d4 = (slot >> 7) << 2;
            int n = win_token(w, kt * 128 + r);
            float4 kv = *(const float4*)(qkv + (size_t)n * 3072 + 1024 + head * 64 + d4);
            float* kd = sm + KTOFF;
            kd[(d4 + 0) * 130 + r] = kv.x;
            kd[(d4 + 1) * 130 + r] = kv.y;
            kd[(d4 + 2) * 130 + r] = kv.z;
            kd[(d4 + 3) * 130 + r] = kv.w;
        }
#pragma unroll
        for (int i = 0; i < 8; i++) {
            int slot = tid + i * 256;
            int r = slot >> 4;
            int d4 = (slot & 15) << 2;
            int n = win_token(w, kt * 128 + r);
            float4 vv = *(const float4*)(qkv + (size_t)n * 3072 + 2048 + head * 64 + d4);
            *(float4*)(sm + VOFF + r * 68 + d4) = vv;
        }
        __syncthreads();

        // --- S = Q K^T : pairs along q (qv2), broadcast keys ---
        {
            ull sr2[4][8];
#pragma unroll
            for (int ii = 0; ii < 4; ii++)
#pragma unroll
                for (int jj = 0; jj < 8; jj++) sr2[ii][jj] = 0ull;

            const float* qp = sm + QTOFF + ty * 8;
            const float* kp = sm + KTOFF + tx;
#pragma unroll 4
            for (int d = 0; d < 64; ++d) {
                ull qv[4];
#pragma unroll
                for (int ii = 0; ii < 4; ii++)
                    qv[ii] = ((const ull*)qp)[ii];
                ull kb[8];
#pragma unroll
                for (int jj = 0; jj < 8; jj++)
                    kb[jj] = bcast2(kp[16 * jj]);
#pragma unroll
                for (int ii = 0; ii < 4; ii++)
#pragma unroll
                    for (int jj = 0; jj < 8; jj++)
                        fma2(sr2[ii][jj], qv[ii], kb[jj]);
                qp += 130; kp += 130;
            }

            // store S [q][key], pad 130
#pragma unroll
            for (int ii = 0; ii < 4; ii++) {
                int q0 = ty * 8 + 2 * ii;
#pragma unroll
                for (int jj = 0; jj < 8; jj++) {
                    F2U u; u.u = sr2[ii][jj];
                    int kc = tx + 16 * jj;
                    sm[SOFF + q0 * 130 + kc]       = u.f.x;
                    sm[SOFF + (q0 + 1) * 130 + kc] = u.f.y;
                }
            }
        }
        __syncthreads();

        // --- exp + row sums (2 threads per row) ---
        {
            int r = tid >> 1;
            int hh = (tid & 1) << 6;
            float* srow = sm + SOFF + r * 130 + hh;
            float ssum = 0.f;
#pragma unroll 8
            for (int k2 = 0; k2 < 64; k2++) {
                float p = __expf(srow[k2]);
                srow[k2] = p;
                ssum += p;
            }
            ssum += __shfl_xor_sync(0xffffffffu, ssum, 1);
            if ((tid & 1) == 0) sm[LOFF + r] += ssum;
        }
        __syncthreads();

        // --- acc += P * V : pairs along d, broadcast P ---
        {
            const float* pp = sm + SOFF + pr * 130;
            const float* vp = sm + VOFF + pc4;
#pragma unroll 4
            for (int kk = 0; kk < 128; ++kk) {
                const ull* v0p = (const ull*)(vp + kk * 68);
                const ull* v1p = (const ull*)(vp + kk * 68 + 32);
                ull v0 = v0p[0], v1 = v0p[1];
                ull v2 = v1p[0], v3 = v1p[1];
                ull pb[4];
#pragma unroll
                for (int i = 0; i < 4; i++)
                    pb[i] = bcast2(pp[i * 130 + kk]);
#pragma unroll
                for (int i = 0; i < 4; i++) {
                    fma2(oacc[i][0], v0, pb[i]);
                    fma2(oacc[i][1], v1, pb[i]);
                    fma2(oacc[i][2], v2, pb[i]);
                    fma2(oacc[i][3], v3, pb[i]);
                }
            }
        }
    }

    // --- normalize and write h in token order ---
#pragma unroll
    for (int i = 0; i < 4; i++) {
        int rr = pr + i;
        float linv = 1.0f / sm[LOFF + rr];
        int n = win_token(w, qc * 128 + rr);
        float* op = hout + (size_t)n * 1024 + head * 64 + pc4;
        F2U a0, a1, a2, a3;
        a0.u = oacc[i][0]; a1.u = oacc[i][1];
        a2.u = oacc[i][2]; a3.u = oacc[i][3];
        float4 o1, o2;
        o1.x = a0.f.x * linv; o1.y = a0.f.y * linv;
        o1.z = a1.f.x * linv; o1.w = a1.f.y * linv;
        o2.x = a2.f.x * linv; o2.y = a2.f.y * linv;
        o2.z = a3.f.x * linv; o2.w = a3.f.y * linv;
        *(float4*)op = o1;
        *(float4*)(op + 32) = o2;
    }
}

// ---------------- launch ----------------------------------------------------
extern "C" void kernel_launch(void* const* d_in, const int* in_sizes, int n_in,
                              void* d_out, int out_size)
{
    const float* x      = (const float*)d_in[0];
    const int*   coords = (const int*)d_in[1];
    const float* Wqkv   = (const float*)d_in[2];
    const float* bqkv   = (const float*)d_in[3];
    const float* gq     = (const float*)d_in[4];
    const float* gk     = (const float*)d_in[5];
    const float* Wout   = (const float*)d_in[6];
    const float* bout   = (const float*)d_in[7];
    float* out = (float*)d_out;

    cudaFuncSetAttribute(gemm_tf32_kernel, cudaFuncAttributeMaxDynamicSharedMemorySize, GEMM_SMEM);
    cudaFuncSetAttribute(attn_kernel, cudaFuncAttributeMaxDynamicSharedMemorySize, ATTN_SMEM);

    float *qkv_ptr = nullptr, *h_ptr = nullptr;
    cudaGetSymbolAddress((void**)&qkv_ptr, g_qkv);
    cudaGetSymbolAddress((void**)&h_ptr, g_hbuf);

    // 1) qkv = x @ Wqkv + bqkv
    gemm_tf32_kernel<<<dim3(3072 / 128, NTOK / 128), 256, GEMM_SMEM>>>(
        x, Wqkv, bqkv, qkv_ptr, NTOK, 3072, CDIM);

    // 2) in-place RMSNorm + RoPE on q,k
    normrope_kernel<<<(NTOK * NHEAD) / 8, 256>>>(qkv_ptr, coords, gq, gk);

    // 3) windowed attention -> h (token order)
    attn_kernel<<<64 * 16 * 4, 256, ATTN_SMEM>>>(qkv_ptr, h_ptr);

    // 4) out = h @ Wout + bout
    gemm_tf32_kernel<<<dim3(1024 / 128, NTOK / 128), 256, GEMM_SMEM>>>(
        h_ptr, Wout, bout, out, NTOK, 1024, CDIM);
}

// round 6
// speedup vs baseline: 1.5054x; 1.0274x over previous
#include <cuda_runtime.h>
#include <cstdint>
#include <math.h>

#define NTOK 32768
#define CDIM 1024
#define NHEAD 16
#define HD 64

// ---------------- scratch ---------------------------------------------------
__device__ float g_qkv[NTOK * 3 * CDIM];   // GEMM1 out (natural layout)
__device__ float g_hbuf[NTOK * CDIM];      // attn out (tf32-rounded, k-interleaved)
__device__ float g_xt[NTOK * CDIM];        // x, tf32-rounded, k-interleaved
__device__ float g_w1[CDIM * 3 * CDIM];    // Wqkv, tf32-rounded (natural)
__device__ float g_w2[CDIM * CDIM];        // Wout, tf32-rounded (natural)

// ---------------- helpers ---------------------------------------------------
__device__ __forceinline__ uint32_t f2tfu(float x) {
    uint32_t u;
    asm("cvt.rna.tf32.f32 %0, %1;" : "=r"(u) : "f"(x));
    return u;
}
__device__ __forceinline__ float f2tf(float x) { return __uint_as_float(f2tfu(x)); }

__device__ __forceinline__ void mma_tf32(float* d, const uint32_t* a, const uint32_t* b) {
    asm volatile(
        "mma.sync.aligned.m16n8k8.row.col.f32.tf32.tf32.f32 "
        "{%0,%1,%2,%3}, {%4,%5,%6,%7}, {%8,%9}, {%0,%1,%2,%3};\n"
        : "+f"(d[0]), "+f"(d[1]), "+f"(d[2]), "+f"(d[3])
        : "r"(a[0]), "r"(a[1]), "r"(a[2]), "r"(a[3]), "r"(b[0]), "r"(b[1]));
}

__device__ __forceinline__ void cpasync16(uint32_t dst, const void* src) {
    asm volatile("cp.async.cg.shared.global [%0], [%1], 16;" :: "r"(dst), "l"(src));
}
#define CP_COMMIT() asm volatile("cp.async.commit_group;")

typedef unsigned long long ull;
union F2U { float2 f; ull u; };
__device__ __forceinline__ void fma2(ull& d, ull a, ull b) {
    asm("fma.rn.f32x2 %0, %1, %2, %0;" : "+l"(d) : "l"(a), "l"(b));
}
__device__ __forceinline__ ull bcast2(float x) {
    ull r;
    asm("mov.b64 %0, {%1, %1};" : "=l"(r) : "r"(__float_as_uint(x)));
    return r;
}
__device__ __forceinline__ ull pack2(float x, float y) {
    F2U u; u.f.x = x; u.f.y = y; return u.u;
}

// ---------------- GEMM: C[M,N] = A[M,K]*B[K,N] + bias[N] (tf32 MMA) --------
// A pre-rounded + k-interleaved (per-8 group order 0,4,1,5,2,6,3,7),
// B pre-rounded natural. 128x128 tile, K-tile 32, cp.async double-buffer.
#define APAD 72
#define BPAD 136
#define A_TILE (128 * APAD)     // 9216 floats
#define B_TILE (32 * BPAD)      // 4352 floats
#define GEMM_SMEM ((2 * A_TILE + 2 * B_TILE) * 4)   // 108544 bytes

__global__ __launch_bounds__(256, 2)
void gemm_tf32_kernel(const float* __restrict__ A, const float* __restrict__ B,
                      const float* __restrict__ bias, float* __restrict__ Cmat,
                      int M, int N, int K)
{
    extern __shared__ float sgm[];
    const uint32_t sbase = (uint32_t)__cvta_generic_to_shared(sgm);
    const int tid  = threadIdx.x;
    const int lane = tid & 31, warp = tid >> 5;
    const int g    = lane >> 2, tg = lane & 3;
    const int wr   = warp >> 2, wc = warp & 3;
    const int rowBase = blockIdx.y * 128;
    const int colBase = blockIdx.x * 128;
    const int NT = K >> 5;

    float acc[4][4][4];
#pragma unroll
    for (int mi = 0; mi < 4; mi++)
#pragma unroll
        for (int ni = 0; ni < 4; ni++)
#pragma unroll
            for (int q = 0; q < 4; q++) acc[mi][ni][q] = 0.f;

    const int arow = tid >> 3, ac4 = (tid & 7) << 2;
    const int bkb  = tid >> 5, bcc = (tid & 31) << 2;

    auto issue = [&](int kt, int buf) {
        uint32_t sA = sbase + (uint32_t)(buf * A_TILE) * 4u;
        uint32_t sB = sbase + (uint32_t)(2 * A_TILE + buf * B_TILE) * 4u;
#pragma unroll
        for (int i = 0; i < 4; i++) {
            int r = arow + i * 32;
            cpasync16(sA + (uint32_t)(r * APAD + ac4) * 4u,
                      A + (size_t)(rowBase + r) * K + kt * 32 + ac4);
            int kb = bkb + i * 8;
            cpasync16(sB + (uint32_t)(kb * BPAD + bcc) * 4u,
                      B + (size_t)(kt * 32 + kb) * N + colBase + bcc);
        }
        CP_COMMIT();
    };

    issue(0, 0);
    issue(1, 1);

    for (int kt = 0; kt < NT; ++kt) {
        if (kt < NT - 1) asm volatile("cp.async.wait_group 1;");
        else             asm volatile("cp.async.wait_group 0;");
        __syncthreads();

        const float* As = sgm + (kt & 1) * A_TILE;
        const float* Bs = sgm + 2 * A_TILE + (kt & 1) * B_TILE;

#pragma unroll
        for (int ks = 0; ks < 4; ++ks) {
            const int k0 = ks * 8;
            uint32_t af[4][4], bf[4][2];
#pragma unroll
            for (int mi = 0; mi < 4; mi++) {
                // k-interleaved: positions (k0+2tg, k0+2tg+1) = channels (tg, tg+4)
                const float* ap = As + (wr * 64 + mi * 16 + g) * APAD + k0 + 2 * tg;
                float2 lo = *(const float2*)ap;
                float2 hi = *(const float2*)(ap + 8 * APAD);
                af[mi][0] = __float_as_uint(lo.x);
                af[mi][2] = __float_as_uint(lo.y);
                af[mi][1] = __float_as_uint(hi.x);
                af[mi][3] = __float_as_uint(hi.y);
            }
#pragma unroll
            for (int ni = 0; ni < 4; ni++) {
                const float* bp = Bs + (k0 + tg) * BPAD + wc * 32 + ni * 8 + g;
                bf[ni][0] = __float_as_uint(bp[0]);
                bf[ni][1] = __float_as_uint(bp[4 * BPAD]);
            }
#pragma unroll
            for (int mi = 0; mi < 4; mi++)
#pragma unroll
                for (int ni = 0; ni < 4; ni++)
                    mma_tf32(acc[mi][ni], af[mi], bf[ni]);
        }
        __syncthreads();
        if (kt + 2 < NT) issue(kt + 2, kt & 1);
    }

    // epilogue
#pragma unroll
    for (int mi = 0; mi < 4; mi++) {
        int r0 = rowBase + wr * 64 + mi * 16 + g;
#pragma unroll
        for (int ni = 0; ni < 4; ni++) {
            int c0 = colBase + wc * 32 + ni * 8 + tg * 2;
            float b0 = __ldg(bias + c0), b1 = __ldg(bias + c0 + 1);
            float2 v;
            v.x = acc[mi][ni][0] + b0; v.y = acc[mi][ni][1] + b1;
            *(float2*)(Cmat + (size_t)r0 * N + c0) = v;
            v.x = acc[mi][ni][2] + b0; v.y = acc[mi][ni][3] + b1;
            *(float2*)(Cmat + (size_t)(r0 + 8) * N + c0) = v;
        }
    }
}

// ---------------- prepasses -------------------------------------------------
// x: tf32-round + per-8-group k-interleave (pos p holds channel (p>>1)|((p&1)<<2))
__global__ __launch_bounds__(256)
void prep_x_kernel(const float* __restrict__ in, float* __restrict__ out, int n)
{
    int i = blockIdx.x * 256 + threadIdx.x;
    int stride = gridDim.x * 256;
    for (; i < n; i += stride) {
        int c = i & (CDIM - 1);
        int p = c & 7;
        int ic = (c & ~7) | ((p >> 1) | ((p & 1) << 2));
        out[i] = f2tf(in[(i & ~(CDIM - 1)) | ic]);
    }
}

// weights: elementwise tf32-round (float4)
__global__ __launch_bounds__(256)
void prep_w_kernel(const float* __restrict__ in, float* __restrict__ out, int n4)
{
    int i = blockIdx.x * 256 + threadIdx.x;
    int stride = gridDim.x * 256;
    for (; i < n4; i += stride) {
        float4 v = ((const float4*)in)[i];
        v.x = f2tf(v.x); v.y = f2tf(v.y); v.z = f2tf(v.z); v.w = f2tf(v.w);
        ((float4*)out)[i] = v;
    }
}

// ---------------- RMSNorm + RoPE, in place on q,k --------------------------
__global__ __launch_bounds__(256)
void normrope_kernel(float* __restrict__ qkv, const int* __restrict__ coords,
                     const float* __restrict__ gq, const float* __restrict__ gk)
{
    const int wid  = blockIdx.x * 8 + (threadIdx.x >> 5);
    const int lane = threadIdx.x & 31;
    const int n = wid >> 4;
    const int h = wid & 15;

    const int j = lane;
    float c = 1.f, s = 0.f;
    if (j < 30) {
        int axis = (j >= 20) ? 2 : ((j >= 10) ? 1 : 0);
        int f = j - axis * 10;
        float freq = exp2f((float)f * -1.32877123795494493f);
        float phase = (float)__ldg(coords + n * 3 + axis) * freq;
        sincosf(phase, &s, &c);
    }

    float* qp = qkv + (size_t)n * 3072 + h * 64;

#pragma unroll
    for (int pass = 0; pass < 2; ++pass) {
        float* p = qp + pass * 1024;
        const float* gamma = (pass == 0 ? gq : gk) + h * 64;
        float2 t = *(float2*)(p + 2 * j);
        float ss = t.x * t.x + t.y * t.y;
#pragma unroll
        for (int o = 16; o > 0; o >>= 1) ss += __shfl_xor_sync(0xffffffffu, ss, o);
        float inv = 8.0f / fmaxf(sqrtf(ss), 1e-12f);
        float v0 = t.x * inv * __ldg(gamma + 2 * j);
        float v1 = t.y * inv * __ldg(gamma + 2 * j + 1);
        float2 o2;
        o2.x = v0 * c - v1 * s;
        o2.y = v0 * s + v1 * c;
        *(float2*)(p + 2 * j) = o2;
    }
}

// ---------------- windowed attention (fp32x2 + cp.async pipeline) ----------
// smem floats: Qt [64][132], Kt [64][132], Kstg [128][68], V [128][68],
//              S [128][130], L [128]
#define QTOFF 0
#define KTOFF 8448
#define KSTG  16896
#define VOFF  25600
#define SOFF  34304
#define LOFF  50944
#define ATTN_SMEM (51072 * 4)   // 204288 bytes

__device__ __forceinline__ int win_token(int w, int p) {
    int wx = w >> 4, wy = (w >> 2) & 3, wz = w & 3;
    int px = p >> 6, py = (p >> 3) & 7, pz = p & 7;
    return ((((wx << 3) + px) << 10) | (((wy << 3) + py) << 5) | ((wz << 3) + pz));
}

__global__ __launch_bounds__(256, 1)
void attn_kernel(const float* __restrict__ qkv, float* __restrict__ hout)
{
    extern __shared__ float sm[];
    const uint32_t sbase = (uint32_t)__cvta_generic_to_shared(sm);
    const int tid  = threadIdx.x;
    const int b    = blockIdx.x;
    const int qc   = b & 3;
    const int head = (b >> 2) & 15;
    const int w    = b >> 6;

    // async-copy issue helpers: K -> staging [key][68], V -> V region [key][68]
    auto issue_k = [&](int kt) {
#pragma unroll
        for (int i = 0; i < 8; i++) {
            int slot = tid + i * 256;
            int r = slot >> 4, d4 = (slot & 15) << 2;
            int n = win_token(w, kt * 128 + r);
            cpasync16(sbase + (uint32_t)(KSTG + r * 68 + d4) * 4u,
                      qkv + (size_t)n * 3072 + 1024 + head * 64 + d4);
        }
        CP_COMMIT();
    };
    auto issue_v = [&](int kt) {
#pragma unroll
        for (int i = 0; i < 8; i++) {
            int slot = tid + i * 256;
            int r = slot >> 4, d4 = (slot & 15) << 2;
            int n = win_token(w, kt * 128 + r);
            cpasync16(sbase + (uint32_t)(VOFF + r * 68 + d4) * 4u,
                      qkv + (size_t)n * 3072 + 2048 + head * 64 + d4);
        }
        CP_COMMIT();
    };

    issue_k(0);
    issue_v(0);

    // Q load (plain LDG, overlaps with the cp.asyncs), transposed [d][132], /8
#pragma unroll
    for (int i = 0; i < 8; i++) {
        int slot = tid + i * 256;
        int r = slot & 127;
        int d4 = (slot >> 7) << 2;
        int n = win_token(w, qc * 128 + r);
        float4 v = *(const float4*)(qkv + (size_t)n * 3072 + head * 64 + d4);
        float* dst = sm + QTOFF;
        dst[(d4 + 0) * 132 + r] = v.x * 0.125f;
        dst[(d4 + 1) * 132 + r] = v.y * 0.125f;
        dst[(d4 + 2) * 132 + r] = v.z * 0.125f;
        dst[(d4 + 3) * 132 + r] = v.w * 0.125f;
    }
    if (tid < 128) sm[LOFF + tid] = 0.f;

    const int pr  = (tid >> 3) << 2;
    const int pc4 = (tid & 7) << 2;
    ull oacc[4][4];
#pragma unroll
    for (int i = 0; i < 4; i++)
#pragma unroll
        for (int jj = 0; jj < 4; jj++) oacc[i][jj] = 0ull;

    const int ty = tid >> 4, tx = tid & 15;

    for (int kt = 0; kt < 4; ++kt) {
        // Kstg(kt) arrived (allow V(kt) pending); also PV(kt-1) done via sync
        asm volatile("cp.async.wait_group 1;");
        __syncthreads();

        // transpose staging [key][68] -> Kt [d][132]
#pragma unroll
        for (int i = 0; i < 8; i++) {
            int slot = tid + i * 256;
            int r = slot & 127;
            int d4 = (slot >> 7) << 2;
            float4 kv = *(const float4*)(sm + KSTG + r * 68 + d4);
            float* kd = sm + KTOFF;
            kd[(d4 + 0) * 132 + r] = kv.x;
            kd[(d4 + 1) * 132 + r] = kv.y;
            kd[(d4 + 2) * 132 + r] = kv.z;
            kd[(d4 + 3) * 132 + r] = kv.w;
        }
        __syncthreads();

        if (kt < 3) issue_k(kt + 1);    // staging free; overlaps S compute

        // --- S = Q K^T : pairs along q, broadcast keys ---
        {
            ull sr2[4][8];
#pragma unroll
            for (int ii = 0; ii < 4; ii++)
#pragma unroll
                for (int jj = 0; jj < 8; jj++) sr2[ii][jj] = 0ull;

            const float* qp = sm + QTOFF + ty * 8;
            const float* kp = sm + KTOFF + tx;
#pragma unroll 4
            for (int d = 0; d < 64; ++d) {
                float4 qa = *(const float4*)qp;
                float4 qb = *(const float4*)(qp + 4);
                ull qv[4];
                qv[0] = pack2(qa.x, qa.y); qv[1] = pack2(qa.z, qa.w);
                qv[2] = pack2(qb.x, qb.y); qv[3] = pack2(qb.z, qb.w);
                ull kb[8];
#pragma unroll
                for (int jj = 0; jj < 8; jj++)
                    kb[jj] = bcast2(kp[16 * jj]);
#pragma unroll
                for (int ii = 0; ii < 4; ii++)
#pragma unroll
                    for (int jj = 0; jj < 8; jj++)
                        fma2(sr2[ii][jj], qv[ii], kb[jj]);
                qp += 132; kp += 132;
            }

#pragma unroll
            for (int ii = 0; ii < 4; ii++) {
                int q0 = ty * 8 + 2 * ii;
#pragma unroll
                for (int jj = 0; jj < 8; jj++) {
                    F2U u; u.u = sr2[ii][jj];
                    int kc = tx + 16 * jj;
                    sm[SOFF + q0 * 130 + kc]       = u.f.x;
                    sm[SOFF + (q0 + 1) * 130 + kc] = u.f.y;
                }
            }
        }
        __syncthreads();

        // --- exp + row sums ---
        {
            int r = tid >> 1;
            int hh = (tid & 1) << 6;
            float* srow = sm + SOFF + r * 130 + hh;
            float ssum = 0.f;
#pragma unroll 8
            for (int k2 = 0; k2 < 64; k2++) {
                float p = __expf(srow[k2]);
                srow[k2] = p;
                ssum += p;
            }
            ssum += __shfl_xor_sync(0xffffffffu, ssum, 1);
            if ((tid & 1) == 0) sm[LOFF + r] += ssum;
        }
        // V(kt) must be complete before PV (oldest pending group)
        if (kt < 3) asm volatile("cp.async.wait_group 1;");
        else        asm volatile("cp.async.wait_group 0;");
        __syncthreads();

        // --- acc += P * V ---
        {
            const float* pp = sm + SOFF + pr * 130;
            const float* vp = sm + VOFF + pc4;
#pragma unroll 4
            for (int kk = 0; kk < 128; ++kk) {
                float4 va = *(const float4*)(vp + kk * 68);
                float4 vb = *(const float4*)(vp + kk * 68 + 32);
                ull v0 = pack2(va.x, va.y), v1 = pack2(va.z, va.w);
                ull v2 = pack2(vb.x, vb.y), v3 = pack2(vb.z, vb.w);
                ull pb[4];
#pragma unroll
                for (int i = 0; i < 4; i++)
                    pb[i] = bcast2(pp[i * 130 + kk]);
#pragma unroll
                for (int i = 0; i < 4; i++) {
                    fma2(oacc[i][0], v0, pb[i]);
                    fma2(oacc[i][1], v1, pb[i]);
                    fma2(oacc[i][2], v2, pb[i]);
                    fma2(oacc[i][3], v3, pb[i]);
                }
            }
        }
        __syncthreads();                 // PV done; V region free
        if (kt < 3) issue_v(kt + 1);     // overlaps next transpose/S
    }

    // normalize, tf32-round, write h k-INTERLEAVED (GEMM2 A layout)
    // channel c -> group base + 2*(c&3) + ((c>>2)&1); our 4 channels pc4..pc4+3
    // share a group half: positions odd + {0,2,4,6}
    const int odd = (pc4 >> 2) & 1;
    const int cbase = head * 64 + (pc4 & ~7);
#pragma unroll
    for (int i = 0; i < 4; i++) {
        int rr = pr + i;
        float linv = 1.0f / sm[LOFF + rr];
        int n = win_token(w, qc * 128 + rr);
        float* op = hout + (size_t)n * 1024 + cbase + odd;
        F2U a0, a1, a2, a3;
        a0.u = oacc[i][0]; a1.u = oacc[i][1];
        a2.u = oacc[i][2]; a3.u = oacc[i][3];
        op[0]  = f2tf(a0.f.x * linv);
        op[2]  = f2tf(a0.f.y * linv);
        op[4]  = f2tf(a1.f.x * linv);
        op[6]  = f2tf(a1.f.y * linv);
        op[32] = f2tf(a2.f.x * linv);
        op[34] = f2tf(a2.f.y * linv);
        op[36] = f2tf(a3.f.x * linv);
        op[38] = f2tf(a3.f.y * linv);
    }
}

// ---------------- launch ----------------------------------------------------
extern "C" void kernel_launch(void* const* d_in, const int* in_sizes, int n_in,
                              void* d_out, int out_size)
{
    const float* x      = (const float*)d_in[0];
    const int*   coords = (const int*)d_in[1];
    const float* Wqkv   = (const float*)d_in[2];
    const float* bqkv   = (const float*)d_in[3];
    const float* gq     = (const float*)d_in[4];
    const float* gk     = (const float*)d_in[5];
    const float* Wout   = (const float*)d_in[6];
    const float* bout   = (const float*)d_in[7];
    float* out = (float*)d_out;

    cudaFuncSetAttribute(gemm_tf32_kernel, cudaFuncAttributeMaxDynamicSharedMemorySize, GEMM_SMEM);
    cudaFuncSetAttribute(attn_kernel, cudaFuncAttributeMaxDynamicSharedMemorySize, ATTN_SMEM);

    float *qkv_ptr, *h_ptr, *xt_ptr, *w1_ptr, *w2_ptr;
    cudaGetSymbolAddress((void**)&qkv_ptr, g_qkv);
    cudaGetSymbolAddress((void**)&h_ptr, g_hbuf);
    cudaGetSymbolAddress((void**)&xt_ptr, g_xt);
    cudaGetSymbolAddress((void**)&w1_ptr, g_w1);
    cudaGetSymbolAddress((void**)&w2_ptr, g_w2);

    // prepasses
    prep_x_kernel<<<8192, 256>>>(x, xt_ptr, NTOK * CDIM);
    prep_w_kernel<<<4096, 256>>>(Wqkv, w1_ptr, CDIM * 3 * CDIM / 4);
    prep_w_kernel<<<2048, 256>>>(Wout, w2_ptr, CDIM * CDIM / 4);

    // 1) qkv = x @ Wqkv + bqkv
    gemm_tf32_kernel<<<dim3(3072 / 128, NTOK / 128), 256, GEMM_SMEM>>>(
        xt_ptr, w1_ptr, bqkv, qkv_ptr, NTOK, 3072, CDIM);

    // 2) RMSNorm + RoPE in place
    normrope_kernel<<<(NTOK * NHEAD) / 8, 256>>>(qkv_ptr, coords, gq, gk);

    // 3) windowed attention -> h (interleaved + rounded)
    attn_kernel<<<64 * 16 * 4, 256, ATTN_SMEM>>>(qkv_ptr, h_ptr);

    // 4) out = h @ Wout + bout
    gemm_tf32_kernel<<<dim3(1024 / 128, NTOK / 128), 256, GEMM_SMEM>>>(
        h_ptr, w2_ptr, bout, out, NTOK, 1024, CDIM);
}

// round 7
// speedup vs baseline: 1.7551x; 1.1659x over previous
#include <cuda_runtime.h>
#include <cuda_fp16.h>
#include <cstdint>
#include <math.h>

#define NTOK 32768
#define CDIM 1024
#define NHEAD 16
#define HD 64

// ---------------- scratch ---------------------------------------------------
__device__ float  g_qkv[NTOK * 3 * CDIM];        // GEMM1 out fp32
__device__ __half g_h16[NTOK * CDIM];            // attn out, fp16
__device__ __half g_x16[NTOK * CDIM];            // x, fp16
__device__ __half g_w1p[CDIM * 3 * CDIM];        // Wqkv pair-packed [K/2][N] as half2
__device__ __half g_w2p[CDIM * CDIM];            // Wout pair-packed

// ---------------- helpers ---------------------------------------------------
__device__ __forceinline__ void mma_f16(float* d, const uint32_t* a, const uint32_t* b) {
    asm volatile(
        "mma.sync.aligned.m16n8k16.row.col.f32.f16.f16.f32 "
        "{%0,%1,%2,%3}, {%4,%5,%6,%7}, {%8,%9}, {%0,%1,%2,%3};\n"
        : "+f"(d[0]), "+f"(d[1]), "+f"(d[2]), "+f"(d[3])
        : "r"(a[0]), "r"(a[1]), "r"(a[2]), "r"(a[3]), "r"(b[0]), "r"(b[1]));
}

__device__ __forceinline__ void cpasync16(uint32_t dst, const void* src) {
    asm volatile("cp.async.cg.shared.global [%0], [%1], 16;" :: "r"(dst), "l"(src));
}
#define CP_COMMIT() asm volatile("cp.async.commit_group;")

typedef unsigned long long ull;
union F2U { float2 f; ull u; };
__device__ __forceinline__ void fma2(ull& d, ull a, ull b) {
    asm("fma.rn.f32x2 %0, %1, %2, %0;" : "+l"(d) : "l"(a), "l"(b));
}
__device__ __forceinline__ ull bcast2(float x) {
    ull r;
    asm("mov.b64 %0, {%1, %1};" : "=l"(r) : "r"(__float_as_uint(x)));
    return r;
}
__device__ __forceinline__ ull pack2(float x, float y) {
    F2U u; u.f.x = x; u.f.y = y; return u.u;
}

// ---------------- GEMM: C[M,N] = A[M,K]*Bp + bias[N] (fp16 MMA, fp32 acc) --
// A: half [M][K] natural. Bp: half2-packed [K/2][N].
// CTA tile 128x128, K-tile 32 (2 MMA k-steps), 4-stage cp.async pipeline.
#define APADH 40                       // halves per A smem row (32 data + 8 pad)
#define BPADU 136                      // u32 per B smem row (128 data + 8 pad)
#define A_TILE_B (128 * APADH * 2)     // 10240 bytes
#define B_TILE_B (16 * BPADU * 4)      // 8704 bytes
#define STAGE_B (A_TILE_B + B_TILE_B)  // 18944
#define GEMM_SMEM (4 * STAGE_B)        // 75776

__global__ __launch_bounds__(256, 2)
void gemm_f16_kernel(const __half* __restrict__ A, const __half* __restrict__ Bp,
                     const float* __restrict__ bias, float* __restrict__ Cmat,
                     int M, int N, int K)
{
    extern __shared__ char sgm[];
    const uint32_t sbase = (uint32_t)__cvta_generic_to_shared(sgm);
    const int tid  = threadIdx.x;
    const int lane = tid & 31, warp = tid >> 5;
    const int g    = lane >> 2, tg = lane & 3;
    const int wr   = warp >> 2, wc = warp & 3;
    const int rowBase = blockIdx.y * 128;
    const int colBase = blockIdx.x * 128;          // in u32/half2 units == n
    const int NT = K >> 5;
    const uint32_t* Bp32 = (const uint32_t*)Bp;
    const int Nu = N;                              // u32 per Bp row

    float acc[4][4][4];
#pragma unroll
    for (int mi = 0; mi < 4; mi++)
#pragma unroll
        for (int ni = 0; ni < 4; ni++)
#pragma unroll
            for (int q = 0; q < 4; q++) acc[mi][ni][q] = 0.f;

    // copy mapping: A rows 128, 4 chunks of 16B each (64B data/row)
    const int ar = tid >> 1, ach = (tid & 1) << 1;     // 2 chunks per thread pass
    // B: 16 rows x 32 chunks of 16B
    const int br = tid >> 4, bch = (tid & 15) << 1;

    auto issue = [&](int kt) {
        const int slot = kt & 3;
        const uint32_t sA = sbase + slot * STAGE_B;
        const uint32_t sB = sA + A_TILE_B;
#pragma unroll
        for (int c = 0; c < 2; c++) {
            cpasync16(sA + (uint32_t)(ar * APADH * 2 + (ach + c) * 16),
                      A + (size_t)(rowBase + ar) * K + kt * 32 + (ach + c) * 8);
            cpasync16(sB + (uint32_t)(br * BPADU * 4 + (bch + c) * 16),
                      Bp32 + (size_t)(kt * 16 + br) * Nu + colBase + (bch + c) * 4);
        }
        CP_COMMIT();
    };

    issue(0); issue(1); issue(2);

    for (int kt = 0; kt < NT; ++kt) {
        asm volatile("cp.async.wait_group 2;");
        __syncthreads();
        if (kt + 3 < NT) issue(kt + 3);
        else CP_COMMIT();                           // keep group counting uniform

        const uint32_t* As = (const uint32_t*)(sgm + (kt & 3) * STAGE_B);
        const uint32_t* Bs = (const uint32_t*)(sgm + (kt & 3) * STAGE_B + A_TILE_B);

#pragma unroll
        for (int ks = 0; ks < 2; ++ks) {
            uint32_t af[4][4], bf[4][2];
#pragma unroll
            for (int mi = 0; mi < 4; mi++) {
                const uint32_t* ap = As + (wr * 64 + mi * 16 + g) * (APADH / 2) + ks * 8 + tg;
                af[mi][0] = ap[0];                   // (g,   k 2tg..)
                af[mi][2] = ap[4];                   // (g,   k 2tg+8..)
                af[mi][1] = ap[8 * (APADH / 2)];     // (g+8, k 2tg..)
                af[mi][3] = ap[8 * (APADH / 2) + 4]; // (g+8, k 2tg+8..)
            }
#pragma unroll
            for (int ni = 0; ni < 4; ni++) {
                const uint32_t* bp = Bs + (ks * 8 + tg) * BPADU + wc * 32 + ni * 8 + g;
                bf[ni][0] = bp[0];
                bf[ni][1] = bp[4 * BPADU];
            }
#pragma unroll
            for (int mi = 0; mi < 4; mi++)
#pragma unroll
                for (int ni = 0; ni < 4; ni++)
                    mma_f16(acc[mi][ni], af[mi], bf[ni]);
        }
        __syncthreads();
    }

    // epilogue: + bias, fp32 store
#pragma unroll
    for (int mi = 0; mi < 4; mi++) {
        int r0 = rowBase + wr * 64 + mi * 16 + g;
#pragma unroll
        for (int ni = 0; ni < 4; ni++) {
            int c0 = colBase + wc * 32 + ni * 8 + tg * 2;
            float b0 = __ldg(bias + c0), b1 = __ldg(bias + c0 + 1);
            float2 v;
            v.x = acc[mi][ni][0] + b0; v.y = acc[mi][ni][1] + b1;
            *(float2*)(Cmat + (size_t)r0 * N + c0) = v;
            v.x = acc[mi][ni][2] + b0; v.y = acc[mi][ni][3] + b1;
            *(float2*)(Cmat + (size_t)(r0 + 8) * N + c0) = v;
        }
    }
}

// ---------------- prepasses -------------------------------------------------
// x: fp32 -> fp16, natural order
__global__ __launch_bounds__(256)
void prep_x_kernel(const float* __restrict__ in, __half* __restrict__ out, int n8)
{
    int i = blockIdx.x * 256 + threadIdx.x;
    int stride = gridDim.x * 256;
    for (; i < n8; i += stride) {
        float4 a = ((const float4*)in)[2 * i];
        float4 b = ((const float4*)in)[2 * i + 1];
        __half2 h[4];
        h[0] = __floats2half2_rn(a.x, a.y);
        h[1] = __floats2half2_rn(a.z, a.w);
        h[2] = __floats2half2_rn(b.x, b.y);
        h[3] = __floats2half2_rn(b.z, b.w);
        ((uint4*)out)[i] = *(uint4*)h;
    }
}

// W [K][N] fp32 -> pair-packed [K/2][N] half2
__global__ __launch_bounds__(256)
void prep_w_kernel(const float* __restrict__ W, __half* __restrict__ out, int N, int total4)
{
    int i = blockIdx.x * 256 + threadIdx.x;
    int stride = gridDim.x * 256;
    int n4 = N >> 2;
    for (; i < total4; i += stride) {
        int kp = i / n4, j4 = (i - kp * n4) << 2;
        const float* r0 = W + (size_t)(2 * kp) * N + j4;
        const float* r1 = r0 + N;
        float4 a = *(const float4*)r0;
        float4 b = *(const float4*)r1;
        __half2 h[4];
        h[0] = __floats2half2_rn(a.x, b.x);
        h[1] = __floats2half2_rn(a.y, b.y);
        h[2] = __floats2half2_rn(a.z, b.z);
        h[3] = __floats2half2_rn(a.w, b.w);
        ((uint4*)out)[(size_t)kp * n4 + (j4 >> 2)] = *(uint4*)h;
    }
}

// ---------------- RMSNorm + RoPE, in place on q,k --------------------------
__global__ __launch_bounds__(256)
void normrope_kernel(float* __restrict__ qkv, const int* __restrict__ coords,
                     const float* __restrict__ gq, const float* __restrict__ gk)
{
    const int wid  = blockIdx.x * 8 + (threadIdx.x >> 5);
    const int lane = threadIdx.x & 31;
    const int n = wid >> 4;
    const int h = wid & 15;

    const int j = lane;
    float c = 1.f, s = 0.f;
    if (j < 30) {
        int axis = (j >= 20) ? 2 : ((j >= 10) ? 1 : 0);
        int f = j - axis * 10;
        float freq = exp2f((float)f * -1.32877123795494493f);
        float phase = (float)__ldg(coords + n * 3 + axis) * freq;
        sincosf(phase, &s, &c);
    }

    float* qp = qkv + (size_t)n * 3072 + h * 64;

#pragma unroll
    for (int pass = 0; pass < 2; ++pass) {
        float* p = qp + pass * 1024;
        const float* gamma = (pass == 0 ? gq : gk) + h * 64;
        float2 t = *(float2*)(p + 2 * j);
        float ss = t.x * t.x + t.y * t.y;
#pragma unroll
        for (int o = 16; o > 0; o >>= 1) ss += __shfl_xor_sync(0xffffffffu, ss, o);
        float inv = 8.0f / fmaxf(sqrtf(ss), 1e-12f);
        float v0 = t.x * inv * __ldg(gamma + 2 * j);
        float v1 = t.y * inv * __ldg(gamma + 2 * j + 1);
        float2 o2;
        o2.x = v0 * c - v1 * s;
        o2.y = v0 * s + v1 * c;
        *(float2*)(p + 2 * j) = o2;
    }
}

// ---------------- windowed attention (fp32x2 + cp.async pipeline) ----------
#define QTOFF 0
#define KTOFF 8448
#define KSTG  16896
#define VOFF  25600
#define SOFF  34304
#define LOFF  50944
#define ATTN_SMEM (51072 * 4)

__device__ __forceinline__ int win_token(int w, int p) {
    int wx = w >> 4, wy = (w >> 2) & 3, wz = w & 3;
    int px = p >> 6, py = (p >> 3) & 7, pz = p & 7;
    return ((((wx << 3) + px) << 10) | (((wy << 3) + py) << 5) | ((wz << 3) + pz));
}

__global__ __launch_bounds__(256, 1)
void attn_kernel(const float* __restrict__ qkv, __half* __restrict__ hout)
{
    extern __shared__ float sm[];
    const uint32_t sbase = (uint32_t)__cvta_generic_to_shared(sm);
    const int tid  = threadIdx.x;
    const int b    = blockIdx.x;
    const int qc   = b & 3;
    const int head = (b >> 2) & 15;
    const int w    = b >> 6;

    auto issue_k = [&](int kt) {
#pragma unroll
        for (int i = 0; i < 8; i++) {
            int slot = tid + i * 256;
            int r = slot >> 4, d4 = (slot & 15) << 2;
            int n = win_token(w, kt * 128 + r);
            cpasync16(sbase + (uint32_t)(KSTG + r * 68 + d4) * 4u,
                      qkv + (size_t)n * 3072 + 1024 + head * 64 + d4);
        }
        CP_COMMIT();
    };
    auto issue_v = [&](int kt) {
#pragma unroll
        for (int i = 0; i < 8; i++) {
            int slot = tid + i * 256;
            int r = slot >> 4, d4 = (slot & 15) << 2;
            int n = win_token(w, kt * 128 + r);
            cpasync16(sbase + (uint32_t)(VOFF + r * 68 + d4) * 4u,
                      qkv + (size_t)n * 3072 + 2048 + head * 64 + d4);
        }
        CP_COMMIT();
    };

    issue_k(0);
    issue_v(0);

#pragma unroll
    for (int i = 0; i < 8; i++) {
        int slot = tid + i * 256;
        int r = slot & 127;
        int d4 = (slot >> 7) << 2;
        int n = win_token(w, qc * 128 + r);
        float4 v = *(const float4*)(qkv + (size_t)n * 3072 + head * 64 + d4);
        float* dst = sm + QTOFF;
        dst[(d4 + 0) * 132 + r] = v.x * 0.125f;
        dst[(d4 + 1) * 132 + r] = v.y * 0.125f;
        dst[(d4 + 2) * 132 + r] = v.z * 0.125f;
        dst[(d4 + 3) * 132 + r] = v.w * 0.125f;
    }
    if (tid < 128) sm[LOFF + tid] = 0.f;

    const int pr  = (tid >> 3) << 2;
    const int pc4 = (tid & 7) << 2;
    ull oacc[4][4];
#pragma unroll
    for (int i = 0; i < 4; i++)
#pragma unroll
        for (int jj = 0; jj < 4; jj++) oacc[i][jj] = 0ull;

    const int ty = tid >> 4, tx = tid & 15;

    for (int kt = 0; kt < 4; ++kt) {
        asm volatile("cp.async.wait_group 1;");
        __syncthreads();

        // transpose staging [key][68] -> Kt [d][132]
#pragma unroll
        for (int i = 0; i < 8; i++) {
            int slot = tid + i * 256;
            int r = slot & 127;
            int d4 = (slot >> 7) << 2;
            float4 kv = *(const float4*)(sm + KSTG + r * 68 + d4);
            float* kd = sm + KTOFF;
            kd[(d4 + 0) * 132 + r] = kv.x;
            kd[(d4 + 1) * 132 + r] = kv.y;
            kd[(d4 + 2) * 132 + r] = kv.z;
            kd[(d4 + 3) * 132 + r] = kv.w;
        }
        __syncthreads();

        if (kt < 3) issue_k(kt + 1);

        // --- S = Q K^T ---
        {
            ull sr2[4][8];
#pragma unroll
            for (int ii = 0; ii < 4; ii++)
#pragma unroll
                for (int jj = 0; jj < 8; jj++) sr2[ii][jj] = 0ull;

            const float* qp = sm + QTOFF + ty * 8;
            const float* kp = sm + KTOFF + tx;
#pragma unroll 4
            for (int d = 0; d < 64; ++d) {
                float4 qa = *(const float4*)qp;
                float4 qb = *(const float4*)(qp + 4);
                ull qv[4];
                qv[0] = pack2(qa.x, qa.y); qv[1] = pack2(qa.z, qa.w);
                qv[2] = pack2(qb.x, qb.y); qv[3] = pack2(qb.z, qb.w);
                ull kb[8];
#pragma unroll
                for (int jj = 0; jj < 8; jj++)
                    kb[jj] = bcast2(kp[16 * jj]);
#pragma unroll
                for (int ii = 0; ii < 4; ii++)
#pragma unroll
                    for (int jj = 0; jj < 8; jj++)
                        fma2(sr2[ii][jj], qv[ii], kb[jj]);
                qp += 132; kp += 132;
            }

#pragma unroll
            for (int ii = 0; ii < 4; ii++) {
                int q0 = ty * 8 + 2 * ii;
#pragma unroll
                for (int jj = 0; jj < 8; jj++) {
                    F2U u; u.u = sr2[ii][jj];
                    int kc = tx + 16 * jj;
                    sm[SOFF + q0 * 130 + kc]       = u.f.x;
                    sm[SOFF + (q0 + 1) * 130 + kc] = u.f.y;
                }
            }
        }
        __syncthreads();

        // --- exp + row sums ---
        {
            int r = tid >> 1;
            int hh = (tid & 1) << 6;
            float* srow = sm + SOFF + r * 130 + hh;
            float ssum = 0.f;
#pragma unroll 8
            for (int k2 = 0; k2 < 64; k2++) {
                float p = __expf(srow[k2]);
                srow[k2] = p;
                ssum += p;
            }
            ssum += __shfl_xor_sync(0xffffffffu, ssum, 1);
            if ((tid & 1) == 0) sm[LOFF + r] += ssum;
        }
        if (kt < 3) asm volatile("cp.async.wait_group 1;");
        else        asm volatile("cp.async.wait_group 0;");
        __syncthreads();

        // --- acc += P * V ---
        {
            const float* pp = sm + SOFF + pr * 130;
            const float* vp = sm + VOFF + pc4;
#pragma unroll 4
            for (int kk = 0; kk < 128; ++kk) {
                float4 va = *(const float4*)(vp + kk * 68);
                float4 vb = *(const float4*)(vp + kk * 68 + 32);
                ull v0 = pack2(va.x, va.y), v1 = pack2(va.z, va.w);
                ull v2 = pack2(vb.x, vb.y), v3 = pack2(vb.z, vb.w);
                ull pb[4];
#pragma unroll
                for (int i = 0; i < 4; i++)
                    pb[i] = bcast2(pp[i * 130 + kk]);
#pragma unroll
                for (int i = 0; i < 4; i++) {
                    fma2(oacc[i][0], v0, pb[i]);
                    fma2(oacc[i][1], v1, pb[i]);
                    fma2(oacc[i][2], v2, pb[i]);
                    fma2(oacc[i][3], v3, pb[i]);
                }
            }
        }
        __syncthreads();
        if (kt < 3) issue_v(kt + 1);
    }

    // normalize, write h as fp16 (natural order; feeds fp16 GEMM2)
#pragma unroll
    for (int i = 0; i < 4; i++) {
        int rr = pr + i;
        float linv = 1.0f / sm[LOFF + rr];
        int n = win_token(w, qc * 128 + rr);
        __half* op = hout + (size_t)n * 1024 + head * 64 + pc4;
        F2U a0, a1, a2, a3;
        a0.u = oacc[i][0]; a1.u = oacc[i][1];
        a2.u = oacc[i][2]; a3.u = oacc[i][3];
        __half2 h01 = __floats2half2_rn(a0.f.x * linv, a0.f.y * linv);
        __half2 h23 = __floats2half2_rn(a1.f.x * linv, a1.f.y * linv);
        __half2 h45 = __floats2half2_rn(a2.f.x * linv, a2.f.y * linv);
        __half2 h67 = __floats2half2_rn(a3.f.x * linv, a3.f.y * linv);
        *(__half2*)op       = h01;
        *(__half2*)(op + 2) = h23;
        *(__half2*)(op + 32) = h45;
        *(__half2*)(op + 34) = h67;
    }
}

// ---------------- launch ----------------------------------------------------
extern "C" void kernel_launch(void* const* d_in, const int* in_sizes, int n_in,
                              void* d_out, int out_size)
{
    const float* x      = (const float*)d_in[0];
    const int*   coords = (const int*)d_in[1];
    const float* Wqkv   = (const float*)d_in[2];
    const float* bqkv   = (const float*)d_in[3];
    const float* gq     = (const float*)d_in[4];
    const float* gk     = (const float*)d_in[5];
    const float* Wout   = (const float*)d_in[6];
    const float* bout   = (const float*)d_in[7];
    float* out = (float*)d_out;

    cudaFuncSetAttribute(gemm_f16_kernel, cudaFuncAttributeMaxDynamicSharedMemorySize, GEMM_SMEM);
    cudaFuncSetAttribute(attn_kernel, cudaFuncAttributeMaxDynamicSharedMemorySize, ATTN_SMEM);

    float *qkv_ptr;
    __half *h16_ptr, *x16_ptr, *w1p_ptr, *w2p_ptr;
    cudaGetSymbolAddress((void**)&qkv_ptr, g_qkv);
    cudaGetSymbolAddress((void**)&h16_ptr, g_h16);
    cudaGetSymbolAddress((void**)&x16_ptr, g_x16);
    cudaGetSymbolAddress((void**)&w1p_ptr, g_w1p);
    cudaGetSymbolAddress((void**)&w2p_ptr, g_w2p);

    // prepasses
    prep_x_kernel<<<4096, 256>>>(x, x16_ptr, NTOK * CDIM / 8);
    prep_w_kernel<<<4096, 256>>>(Wqkv, w1p_ptr, 3 * CDIM, (CDIM / 2) * (3 * CDIM) / 4);
    prep_w_kernel<<<2048, 256>>>(Wout, w2p_ptr, CDIM, (CDIM / 2) * CDIM / 4);

    // 1) qkv = x @ Wqkv + bqkv   (fp16 MMA)
    gemm_f16_kernel<<<dim3(3072 / 128, NTOK / 128), 256, GEMM_SMEM>>>(
        x16_ptr, w1p_ptr, bqkv, qkv_ptr, NTOK, 3072, CDIM);

    // 2) RMSNorm + RoPE in place (fp32)
    normrope_kernel<<<(NTOK * NHEAD) / 8, 256>>>(qkv_ptr, coords, gq, gk);

    // 3) windowed attention -> h fp16
    attn_kernel<<<64 * 16 * 4, 256, ATTN_SMEM>>>(qkv_ptr, h16_ptr);

    // 4) out = h @ Wout + bout   (fp16 MMA)
    gemm_f16_kernel<<<dim3(1024 / 128, NTOK / 128), 256, GEMM_SMEM>>>(
        h16_ptr, w2p_ptr, bout, out, NTOK, 1024, CDIM);
}

// round 10
// speedup vs baseline: 2.8537x; 1.6260x over previous
#include <cuda_runtime.h>
#include <cuda_fp16.h>
#include <cstdint>
#include <math.h>

#define NTOK 32768
#define CDIM 1024
#define NHEAD 16
#define HD 64

// ---------------- scratch ---------------------------------------------------
__device__ float  g_qkv[NTOK * 3 * CDIM];   // GEMM1 out fp32
__device__ __half g_h16[NTOK * CDIM];       // attn out fp16
__device__ __half g_x16[NTOK * CDIM];       // x fp16
__device__ __half g_w1p[CDIM * 3 * CDIM];   // Wqkv pair-packed
__device__ __half g_w2p[CDIM * CDIM];       // Wout pair-packed
// fp16 hi/lo splits for attention
__device__ __half g_qh[NTOK * CDIM];
__device__ __half g_ql[NTOK * CDIM];
__device__ __half g_kh[NTOK * CDIM];
__device__ __half g_kl[NTOK * CDIM];
__device__ __half g_vh[NTOK * CDIM];
__device__ __half g_vl[NTOK * CDIM];

// ---------------- helpers ---------------------------------------------------
__device__ __forceinline__ void mma_f16(float* d, const uint32_t* a, const uint32_t* b) {
    asm volatile(
        "mma.sync.aligned.m16n8k16.row.col.f32.f16.f16.f32 "
        "{%0,%1,%2,%3}, {%4,%5,%6,%7}, {%8,%9}, {%0,%1,%2,%3};\n"
        : "+f"(d[0]), "+f"(d[1]), "+f"(d[2]), "+f"(d[3])
        : "r"(a[0]), "r"(a[1]), "r"(a[2]), "r"(a[3]), "r"(b[0]), "r"(b[1]));
}

__device__ __forceinline__ void cpasync16(uint32_t dst, const void* src) {
    asm volatile("cp.async.cg.shared.global [%0], [%1], 16;" :: "r"(dst), "l"(src));
}
#define CP_COMMIT() asm volatile("cp.async.commit_group;")

#define LDMX4T(r0, r1, r2, r3, addr) \
    asm volatile("ldmatrix.sync.aligned.m8n8.x4.trans.shared.b16 {%0,%1,%2,%3}, [%4];" \
        : "=r"(r0), "=r"(r1), "=r"(r2), "=r"(r3) : "r"(addr))

__device__ __forceinline__ uint32_t packh2(float a, float b) {
    __half2 h = __floats2half2_rn(a, b);
    return *(uint32_t*)&h;
}

// ---------------- GEMM (fp16 MMA, 4-stage cp.async) -------------------------
#define APADH 40
#define BPADU 136
#define A_TILE_B (128 * APADH * 2)
#define B_TILE_B (16 * BPADU * 4)
#define STAGE_B (A_TILE_B + B_TILE_B)
#define GEMM_SMEM (4 * STAGE_B)

__global__ __launch_bounds__(256, 2)
void gemm_f16_kernel(const __half* __restrict__ A, const __half* __restrict__ Bp,
                     const float* __restrict__ bias, float* __restrict__ Cmat,
                     int M, int N, int K)
{
    extern __shared__ char sgm[];
    const uint32_t sbase = (uint32_t)__cvta_generic_to_shared(sgm);
    const int tid  = threadIdx.x;
    const int lane = tid & 31, warp = tid >> 5;
    const int g    = lane >> 2, tg = lane & 3;
    const int wr   = warp >> 2, wc = warp & 3;
    const int rowBase = blockIdx.y * 128;
    const int colBase = blockIdx.x * 128;
    const int NT = K >> 5;
    const uint32_t* Bp32 = (const uint32_t*)Bp;
    const int Nu = N;

    float acc[4][4][4];
#pragma unroll
    for (int mi = 0; mi < 4; mi++)
#pragma unroll
        for (int ni = 0; ni < 4; ni++)
#pragma unroll
            for (int q = 0; q < 4; q++) acc[mi][ni][q] = 0.f;

    const int ar = tid >> 1, ach = (tid & 1) << 1;
    const int br = tid >> 4, bch = (tid & 15) << 1;

    auto issue = [&](int kt) {
        const int slot = kt & 3;
        const uint32_t sA = sbase + slot * STAGE_B;
        const uint32_t sB = sA + A_TILE_B;
#pragma unroll
        for (int c = 0; c < 2; c++) {
            cpasync16(sA + (uint32_t)(ar * APADH * 2 + (ach + c) * 16),
                      A + (size_t)(rowBase + ar) * K + kt * 32 + (ach + c) * 8);
            cpasync16(sB + (uint32_t)(br * BPADU * 4 + (bch + c) * 16),
                      Bp32 + (size_t)(kt * 16 + br) * Nu + colBase + (bch + c) * 4);
        }
        CP_COMMIT();
    };

    issue(0); issue(1); issue(2);

    for (int kt = 0; kt < NT; ++kt) {
        asm volatile("cp.async.wait_group 2;");
        __syncthreads();
        if (kt + 3 < NT) issue(kt + 3);
        else CP_COMMIT();

        const uint32_t* As = (const uint32_t*)(sgm + (kt & 3) * STAGE_B);
        const uint32_t* Bs = (const uint32_t*)(sgm + (kt & 3) * STAGE_B + A_TILE_B);

#pragma unroll
        for (int ks = 0; ks < 2; ++ks) {
            uint32_t af[4][4], bf[4][2];
#pragma unroll
            for (int mi = 0; mi < 4; mi++) {
                const uint32_t* ap = As + (wr * 64 + mi * 16 + g) * (APADH / 2) + ks * 8 + tg;
                af[mi][0] = ap[0];
                af[mi][2] = ap[4];
                af[mi][1] = ap[8 * (APADH / 2)];
                af[mi][3] = ap[8 * (APADH / 2) + 4];
            }
#pragma unroll
            for (int ni = 0; ni < 4; ni++) {
                const uint32_t* bp = Bs + (ks * 8 + tg) * BPADU + wc * 32 + ni * 8 + g;
                bf[ni][0] = bp[0];
                bf[ni][1] = bp[4 * BPADU];
            }
#pragma unroll
            for (int mi = 0; mi < 4; mi++)
#pragma unroll
                for (int ni = 0; ni < 4; ni++)
                    mma_f16(acc[mi][ni], af[mi], bf[ni]);
        }
        __syncthreads();
    }

#pragma unroll
    for (int mi = 0; mi < 4; mi++) {
        int r0 = rowBase + wr * 64 + mi * 16 + g;
#pragma unroll
        for (int ni = 0; ni < 4; ni++) {
            int c0 = colBase + wc * 32 + ni * 8 + tg * 2;
            float b0 = __ldg(bias + c0), b1 = __ldg(bias + c0 + 1);
            float2 v;
            v.x = acc[mi][ni][0] + b0; v.y = acc[mi][ni][1] + b1;
            *(float2*)(Cmat + (size_t)r0 * N + c0) = v;
            v.x = acc[mi][ni][2] + b0; v.y = acc[mi][ni][3] + b1;
            *(float2*)(Cmat + (size_t)(r0 + 8) * N + c0) = v;
        }
    }
}

// ---------------- prepasses -------------------------------------------------
__global__ __launch_bounds__(256)
void prep_x_kernel(const float* __restrict__ in, __half* __restrict__ out, int n8)
{
    int i = blockIdx.x * 256 + threadIdx.x;
    int stride = gridDim.x * 256;
    for (; i < n8; i += stride) {
        float4 a = ((const float4*)in)[2 * i];
        float4 b = ((const float4*)in)[2 * i + 1];
        __half2 h[4];
        h[0] = __floats2half2_rn(a.x, a.y);
        h[1] = __floats2half2_rn(a.z, a.w);
        h[2] = __floats2half2_rn(b.x, b.y);
        h[3] = __floats2half2_rn(b.z, b.w);
        ((uint4*)out)[i] = *(uint4*)h;
    }
}

__global__ __launch_bounds__(256)
void prep_w_kernel(const float* __restrict__ W, __half* __restrict__ out, int N, int total4)
{
    int i = blockIdx.x * 256 + threadIdx.x;
    int stride = gridDim.x * 256;
    int n4 = N >> 2;
    for (; i < total4; i += stride) {
        int kp = i / n4, j4 = (i - kp * n4) << 2;
        const float* r0 = W + (size_t)(2 * kp) * N + j4;
        const float* r1 = r0 + N;
        float4 a = *(const float4*)r0;
        float4 b = *(const float4*)r1;
        __half2 h[4];
        h[0] = __floats2half2_rn(a.x, b.x);
        h[1] = __floats2half2_rn(a.y, b.y);
        h[2] = __floats2half2_rn(a.z, b.z);
        h[3] = __floats2half2_rn(a.w, b.w);
        ((uint4*)out)[(size_t)kp * n4 + (j4 >> 2)] = *(uint4*)h;
    }
}

// ---------------- RMSNorm + RoPE -> fp16 hi/lo splits -----------------------
__global__ __launch_bounds__(256)
void normrope_kernel(const float* __restrict__ qkv, const int* __restrict__ coords,
                     const float* __restrict__ gq, const float* __restrict__ gk,
                     __half* __restrict__ qh, __half* __restrict__ ql,
                     __half* __restrict__ kh, __half* __restrict__ kl,
                     __half* __restrict__ vh, __half* __restrict__ vl)
{
    const int wid  = blockIdx.x * 8 + (threadIdx.x >> 5);
    const int lane = threadIdx.x & 31;
    const int n = wid >> 4;
    const int h = wid & 15;

    const int j = lane;
    float c = 1.f, s = 0.f;
    if (j < 30) {
        int axis = (j >= 20) ? 2 : ((j >= 10) ? 1 : 0);
        int f = j - axis * 10;
        float freq = exp2f((float)f * -1.32877123795494493f);
        float phase = (float)__ldg(coords + n * 3 + axis) * freq;
        sincosf(phase, &s, &c);
    }

    const float* base = qkv + (size_t)n * 3072 + h * 64;
    const size_t oofs = (size_t)n * 1024 + h * 64 + 2 * j;

    auto store_split = [&](float v0, float v1, __half* hi, __half* lo) {
        __half h0 = __float2half_rn(v0);
        __half h1 = __float2half_rn(v1);
        float r0 = v0 - __half2float(h0);
        float r1 = v1 - __half2float(h1);
        __half2 hv; hv.x = h0; hv.y = h1;
        __half2 lv; lv.x = __float2half_rn(r0); lv.y = __float2half_rn(r1);
        *(__half2*)(hi + oofs) = hv;
        *(__half2*)(lo + oofs) = lv;
    };

#pragma unroll
    for (int pass = 0; pass < 2; ++pass) {
        const float* p = base + pass * 1024;
        const float* gamma = (pass == 0 ? gq : gk) + h * 64;
        float2 t = *(const float2*)(p + 2 * j);
        float ss = t.x * t.x + t.y * t.y;
#pragma unroll
        for (int o = 16; o > 0; o >>= 1) ss += __shfl_xor_sync(0xffffffffu, ss, o);
        float inv = 8.0f / fmaxf(sqrtf(ss), 1e-12f);
        float v0 = t.x * inv * __ldg(gamma + 2 * j);
        float v1 = t.y * inv * __ldg(gamma + 2 * j + 1);
        float r0 = v0 * c - v1 * s;
        float r1 = v0 * s + v1 * c;
        if (pass == 0) store_split(r0 * 0.125f, r1 * 0.125f, qh, ql);
        else           store_split(r0, r1, kh, kl);
    }
    {
        float2 t = *(const float2*)(base + 2048 + 2 * j);
        store_split(t.x, t.y, vh, vl);
    }
}

// ---------------- windowed attention (fp16 HMMA, split-compensated) ---------
#define AT_QH 0
#define AT_QL 18432
#define AT_KV 36864
#define AT_KVBUF 73728
#define ATTN_SMEM 184320

__device__ __forceinline__ int win_token(int w, int p) {
    int wx = w >> 4, wy = (w >> 2) & 3, wz = w & 3;
    int px = p >> 6, py = (p >> 3) & 7, pz = p & 7;
    return ((((wx << 3) + px) << 10) | (((wy << 3) + py) << 5) | ((wz << 3) + pz));
}

__global__ __launch_bounds__(256, 1)
void attn_kernel(const __half* __restrict__ qh, const __half* __restrict__ ql,
                 const __half* __restrict__ kh, const __half* __restrict__ kl,
                 const __half* __restrict__ vh, const __half* __restrict__ vl,
                 __half* __restrict__ hout)
{
    extern __shared__ __align__(16) char smc[];
    const uint32_t sb = (uint32_t)__cvta_generic_to_shared(smc);
    const int tid  = threadIdx.x;
    const int b    = blockIdx.x;
    const int qc   = b & 3;
    const int head = (b >> 2) & 15;
    const int w    = b >> 6;
    const int lane = tid & 31, wid = tid >> 5;
    const int g = lane >> 2, tg = lane & 3;

    auto cp_tile = [&](const __half* src, uint32_t dstB, int pbase) {
#pragma unroll
        for (int i = 0; i < 4; i++) {
            int c = tid + i * 256;
            int r = c >> 3, seg = c & 7;
            int n = win_token(w, pbase + r);
            cpasync16(sb + dstB + (uint32_t)(r * 144 + seg * 16),
                      src + (size_t)n * 1024 + head * 64 + seg * 8);
        }
    };

    cp_tile(qh, AT_QH, qc * 128);
    cp_tile(ql, AT_QL, qc * 128);
    CP_COMMIT();
    cp_tile(kh, AT_KV, 0);
    cp_tile(kl, AT_KV + 18432, 0);
    cp_tile(vh, AT_KV + 36864, 0);
    cp_tile(vl, AT_KV + 55296, 0);
    CP_COMMIT();

    float oacc[8][4];
#pragma unroll
    for (int t = 0; t < 8; t++)
#pragma unroll
        for (int q = 0; q < 4; q++) oacc[t][q] = 0.f;
    float L0 = 0.f, L1 = 0.f;

    const int qrow = wid * 16 + g;
    const uint32_t* qh_g  = (const uint32_t*)(smc + AT_QH) + qrow * 36;
    const uint32_t* qh_g8 = qh_g + 8 * 36;
    const uint32_t* ql_g  = (const uint32_t*)(smc + AT_QL) + qrow * 36;
    const uint32_t* ql_g8 = ql_g + 8 * 36;

    for (int kt = 0; kt < 4; ++kt) {
        if (kt < 3) {
            uint32_t nb = AT_KV + ((kt + 1) & 1) * AT_KVBUF;
            int pb = (kt + 1) * 128;
            cp_tile(kh, nb, pb);
            cp_tile(kl, nb + 18432, pb);
            cp_tile(vh, nb + 36864, pb);
            cp_tile(vl, nb + 55296, pb);
            CP_COMMIT();
            asm volatile("cp.async.wait_group 1;");
        } else {
            asm volatile("cp.async.wait_group 0;");
        }
        __syncthreads();

        const uint32_t kvB = AT_KV + (kt & 1) * AT_KVBUF;
        const uint32_t* KH32 = (const uint32_t*)(smc + kvB);
        const uint32_t* KL32 = (const uint32_t*)(smc + kvB + 18432);
        const uint32_t VHb = sb + kvB + 36864;
        const uint32_t VLb = sb + kvB + 55296;

#pragma unroll
        for (int nh = 0; nh < 2; ++nh) {
            float sacc[8][4];
#pragma unroll
            for (int t = 0; t < 8; t++)
#pragma unroll
                for (int q = 0; q < 4; q++) sacc[t][q] = 0.f;

#pragma unroll
            for (int ks = 0; ks < 4; ++ks) {
                const int c0 = tg + 8 * ks, c1 = tg + 4 + 8 * ks;
                uint32_t ah[4], al[4];
                ah[0] = qh_g[c0];  ah[1] = qh_g8[c0];
                ah[2] = qh_g[c1];  ah[3] = qh_g8[c1];
                al[0] = ql_g[c0];  al[1] = ql_g8[c0];
                al[2] = ql_g[c1];  al[3] = ql_g8[c1];
#pragma unroll
                for (int ni = 0; ni < 8; ++ni) {
                    const int krow = nh * 64 + ni * 8 + g;
                    const uint32_t* kro = KH32 + krow * 36;
                    uint32_t bh[2] = { kro[c0], kro[c1] };
                    const uint32_t* krl = KL32 + krow * 36;
                    uint32_t bl[2] = { krl[c0], krl[c1] };
                    mma_f16(sacc[ni], ah, bh);
                    mma_f16(sacc[ni], al, bh);
                    mma_f16(sacc[ni], ah, bl);
                }
            }

            uint32_t ph[8][2];
#pragma unroll
            for (int t = 0; t < 8; t++) {
                float e0 = __expf(sacc[t][0]);
                float e1 = __expf(sacc[t][1]);
                float e2 = __expf(sacc[t][2]);
                float e3 = __expf(sacc[t][3]);
                L0 += e0 + e1;
                L1 += e2 + e3;
                ph[t][0] = packh2(e0, e1);
                ph[t][1] = packh2(e2, e3);
            }

#pragma unroll
            for (int k = 0; k < 4; ++k) {
                uint32_t pA[4] = { ph[2 * k][0], ph[2 * k][1], ph[2 * k + 1][0], ph[2 * k + 1][1] };
                const int keybase = nh * 64 + 16 * k;
                const int tl = lane >> 3;
                const uint32_t rowoff = (uint32_t)((keybase + (lane & 7) + (tl & 1) * 8) * 144
                                                  + (tl >> 1) * 16);
#pragma unroll
                for (int c = 0; c < 4; ++c) {
                    uint32_t ad = rowoff + c * 32;
                    uint32_t r0, r1, r2, r3;
                    LDMX4T(r0, r1, r2, r3, VHb + ad);
                    { uint32_t bb[2] = { r0, r1 }; mma_f16(oacc[2 * c], pA, bb); }
                    { uint32_t bb[2] = { r2, r3 }; mma_f16(oacc[2 * c + 1], pA, bb); }
                    LDMX4T(r0, r1, r2, r3, VLb + ad);
                    { uint32_t bb[2] = { r0, r1 }; mma_f16(oacc[2 * c], pA, bb); }
                    { uint32_t bb[2] = { r2, r3 }; mma_f16(oacc[2 * c + 1], pA, bb); }
                }
            }
        }
        __syncthreads();
    }

    L0 += __shfl_xor_sync(0xffffffffu, L0, 1);
    L0 += __shfl_xor_sync(0xffffffffu, L0, 2);
    L1 += __shfl_xor_sync(0xffffffffu, L1, 1);
    L1 += __shfl_xor_sync(0xffffffffu, L1, 2);
    const float inv0 = 1.0f / L0;
    const float inv1 = 1.0f / L1;

    const int q0 = qc * 128 + wid * 16 + g;
    const int n0 = win_token(w, q0);
    const int n1 = win_token(w, q0 + 8);
    __half* o0 = hout + (size_t)n0 * 1024 + head * 64 + 2 * tg;
    __half* o1 = hout + (size_t)n1 * 1024 + head * 64 + 2 * tg;
#pragma unroll
    for (int t = 0; t < 8; t++) {
        __half2 h0 = __floats2half2_rn(oacc[t][0] * inv0, oacc[t][1] * inv0);
        __half2 h1 = __floats2half2_rn(oacc[t][2] * inv1, oacc[t][3] * inv1);
        *(__half2*)(o0 + 8 * t) = h0;
        *(__half2*)(o1 + 8 * t) = h1;
    }
}

// ---------------- launch ----------------------------------------------------
extern "C" void kernel_launch(void* const* d_in, const int* in_sizes, int n_in,
                              void* d_out, int out_size)
{
    const float* x      = (const float*)d_in[0];
    const int*   coords = (const int*)d_in[1];
    const float* Wqkv   = (const float*)d_in[2];
    const float* bqkv   = (const float*)d_in[3];
    const float* gq     = (const float*)d_in[4];
    const float* gk     = (const float*)d_in[5];
    const float* Wout   = (const float*)d_in[6];
    const float* bout   = (const float*)d_in[7];
    float* out = (float*)d_out;

    cudaFuncSetAttribute(gemm_f16_kernel, cudaFuncAttributeMaxDynamicSharedMemorySize, GEMM_SMEM);
    cudaFuncSetAttribute(attn_kernel, cudaFuncAttributeMaxDynamicSharedMemorySize, ATTN_SMEM);

    float* qkv_ptr;
    __half *h16, *x16, *w1p, *w2p, *pqh, *pql, *pkh, *pkl, *pvh, *pvl;
    cudaGetSymbolAddress((void**)&qkv_ptr, g_qkv);
    cudaGetSymbolAddress((void**)&h16, g_h16);
    cudaGetSymbolAddress((void**)&x16, g_x16);
    cudaGetSymbolAddress((void**)&w1p, g_w1p);
    cudaGetSymbolAddress((void**)&w2p, g_w2p);
    cudaGetSymbolAddress((void**)&pqh, g_qh);
    cudaGetSymbolAddress((void**)&pql, g_ql);
    cudaGetSymbolAddress((void**)&pkh, g_kh);
    cudaGetSymbolAddress((void**)&pkl, g_kl);
    cudaGetSymbolAddress((void**)&pvh, g_vh);
    cudaGetSymbolAddress((void**)&pvl, g_vl);

    // prepasses
    prep_x_kernel<<<4096, 256>>>(x, x16, NTOK * CDIM / 8);
    prep_w_kernel<<<4096, 256>>>(Wqkv, w1p, 3 * CDIM, (CDIM / 2) * (3 * CDIM) / 4);
    prep_w_kernel<<<2048, 256>>>(Wout, w2p, CDIM, (CDIM / 2) * CDIM / 4);

    // 1) qkv = x @ Wqkv + bqkv
    gemm_f16_kernel<<<dim3(3072 / 128, NTOK / 128), 256, GEMM_SMEM>>>(
        x16, w1p, bqkv, qkv_ptr, NTOK, 3072, CDIM);

    // 2) RMSNorm + RoPE -> fp16 hi/lo splits
    normrope_kernel<<<(NTOK * NHEAD) / 8, 256>>>(qkv_ptr, coords, gq, gk,
                                                 pqh, pql, pkh, pkl, pvh, pvl);

    // 3) windowed attention (fp16 HMMA) -> h fp16
    attn_kernel<<<64 * 16 * 4, 256, ATTN_SMEM>>>(pqh, pql, pkh, pkl, pvh, pvl, h16);

    // 4) out = h @ Wout + bout
    gemm_f16_kernel<<<dim3(1024 / 128, NTOK / 128), 256, GEMM_SMEM>>>(
        h16, w2p, bout, out, NTOK, 1024, CDIM);
}

// round 13
// speedup vs baseline: 2.9967x; 1.0501x over previous
#include <cuda_runtime.h>
#include <cuda_fp16.h>
#include <cstdint>
#include <math.h>

#define NTOK 32768
#define CDIM 1024
#define NHEAD 16
#define HD 64

// ---------------- scratch ---------------------------------------------------
__device__ float  g_qkv[NTOK * 3 * CDIM];   // GEMM1 out fp32
__device__ __half g_h16[NTOK * CDIM];       // attn out fp16
__device__ __half g_x16[NTOK * CDIM];       // x fp16
__device__ __half g_w1p[CDIM * 3 * CDIM];   // Wqkv pair-packed
__device__ __half g_w2p[CDIM * CDIM];       // Wout pair-packed
// fp16 splits for attention (V has no lo part — linear path, fp16 rounding ok)
__device__ __half g_qh[NTOK * CDIM];
__device__ __half g_ql[NTOK * CDIM];
__device__ __half g_kh[NTOK * CDIM];
__device__ __half g_kl[NTOK * CDIM];
__device__ __half g_vh[NTOK * CDIM];

// ---------------- helpers ---------------------------------------------------
__device__ __forceinline__ void mma_f16(float* d, const uint32_t* a, const uint32_t* b) {
    asm volatile(
        "mma.sync.aligned.m16n8k16.row.col.f32.f16.f16.f32 "
        "{%0,%1,%2,%3}, {%4,%5,%6,%7}, {%8,%9}, {%0,%1,%2,%3};\n"
        : "+f"(d[0]), "+f"(d[1]), "+f"(d[2]), "+f"(d[3])
        : "r"(a[0]), "r"(a[1]), "r"(a[2]), "r"(a[3]), "r"(b[0]), "r"(b[1]));
}

__device__ __forceinline__ void cpasync16(uint32_t dst, const void* src) {
    asm volatile("cp.async.cg.shared.global [%0], [%1], 16;" :: "r"(dst), "l"(src));
}
#define CP_COMMIT() asm volatile("cp.async.commit_group;")

#define LDMX4(r0, r1, r2, r3, addr) \
    asm volatile("ldmatrix.sync.aligned.m8n8.x4.shared.b16 {%0,%1,%2,%3}, [%4];" \
        : "=r"(r0), "=r"(r1), "=r"(r2), "=r"(r3) : "r"(addr))

#define LDMX4T(r0, r1, r2, r3, addr) \
    asm volatile("ldmatrix.sync.aligned.m8n8.x4.trans.shared.b16 {%0,%1,%2,%3}, [%4];" \
        : "=r"(r0), "=r"(r1), "=r"(r2), "=r"(r3) : "r"(addr))

__device__ __forceinline__ uint32_t packh2(float a, float b) {
    __half2 h = __floats2half2_rn(a, b);
    return *(uint32_t*)&h;
}

// ---------------- GEMM (fp16 MMA, 4-stage cp.async, ldmatrix A) -------------
#define APADH 40
#define BPADU 136
#define A_TILE_B (128 * APADH * 2)
#define B_TILE_B (16 * BPADU * 4)
#define STAGE_B (A_TILE_B + B_TILE_B)
#define GEMM_SMEM (4 * STAGE_B)

__global__ __launch_bounds__(256, 2)
void gemm_f16_kernel(const __half* __restrict__ A, const __half* __restrict__ Bp,
                     const float* __restrict__ bias, float* __restrict__ Cmat,
                     int M, int N, int K)
{
    extern __shared__ char sgm[];
    const uint32_t sbase = (uint32_t)__cvta_generic_to_shared(sgm);
    const int tid  = threadIdx.x;
    const int lane = tid & 31, warp = tid >> 5;
    const int g    = lane >> 2, tg = lane & 3;
    const int wr   = warp >> 2, wc = warp & 3;
    const int rowBase = blockIdx.y * 128;
    const int colBase = blockIdx.x * 128;
    const int NT = K >> 5;
    const uint32_t* Bp32 = (const uint32_t*)Bp;
    const int Nu = N;

    float acc[4][4][4];
#pragma unroll
    for (int mi = 0; mi < 4; mi++)
#pragma unroll
        for (int ni = 0; ni < 4; ni++)
#pragma unroll
            for (int q = 0; q < 4; q++) acc[mi][ni][q] = 0.f;

    const int ar = tid >> 1, ach = (tid & 1) << 1;
    const int br = tid >> 4, bch = (tid & 15) << 1;

    // ldmatrix lane address base (matrix j = lane>>3: rows (j&1)*8, kbytes (j>>1)*16)
    const uint32_t aRowB = (uint32_t)((wr * 64 + ((lane >> 3) & 1) * 8 + (lane & 7)) * (APADH * 2)
                                      + (lane >> 4) * 16);

    auto issue = [&](int kt) {
        const int slot = kt & 3;
        const uint32_t sA = sbase + slot * STAGE_B;
        const uint32_t sB = sA + A_TILE_B;
#pragma unroll
        for (int c = 0; c < 2; c++) {
            cpasync16(sA + (uint32_t)(ar * APADH * 2 + (ach + c) * 16),
                      A + (size_t)(rowBase + ar) * K + kt * 32 + (ach + c) * 8);
            cpasync16(sB + (uint32_t)(br * BPADU * 4 + (bch + c) * 16),
                      Bp32 + (size_t)(kt * 16 + br) * Nu + colBase + (bch + c) * 4);
        }
        CP_COMMIT();
    };

    issue(0); issue(1); issue(2);

    for (int kt = 0; kt < NT; ++kt) {
        asm volatile("cp.async.wait_group 2;");
        __syncthreads();            // also orders MMA(kt-1) reads before issue below
        if (kt + 3 < NT) issue(kt + 3);
        else CP_COMMIT();

        const uint32_t sAaddr = sbase + (kt & 3) * STAGE_B + aRowB;
        const uint32_t* Bs = (const uint32_t*)(sgm + (kt & 3) * STAGE_B + A_TILE_B);

#pragma unroll
        for (int ks = 0; ks < 2; ++ks) {
            uint32_t af[4][4], bf[4][2];
#pragma unroll
            for (int mi = 0; mi < 4; mi++)
                LDMX4(af[mi][0], af[mi][1], af[mi][2], af[mi][3],
                      sAaddr + (uint32_t)(mi * 16 * (APADH * 2) + ks * 32));
#pragma unroll
            for (int ni = 0; ni < 4; ni++) {
                const uint32_t* bp = Bs + (ks * 8 + tg) * BPADU + wc * 32 + ni * 8 + g;
                bf[ni][0] = bp[0];
                bf[ni][1] = bp[4 * BPADU];
            }
#pragma unroll
            for (int mi = 0; mi < 4; mi++)
#pragma unroll
                for (int ni = 0; ni < 4; ni++)
                    mma_f16(acc[mi][ni], af[mi], bf[ni]);
        }
        // no trailing barrier: next iteration's post-wait barrier protects reuse
    }

#pragma unroll
    for (int mi = 0; mi < 4; mi++) {
        int r0 = rowBase + wr * 64 + mi * 16 + g;
#pragma unroll
        for (int ni = 0; ni < 4; ni++) {
            int c0 = colBase + wc * 32 + ni * 8 + tg * 2;
            float b0 = __ldg(bias + c0), b1 = __ldg(bias + c0 + 1);
            float2 v;
            v.x = acc[mi][ni][0] + b0; v.y = acc[mi][ni][1] + b1;
            *(float2*)(Cmat + (size_t)r0 * N + c0) = v;
            v.x = acc[mi][ni][2] + b0; v.y = acc[mi][ni][3] + b1;
            *(float2*)(Cmat + (size_t)(r0 + 8) * N + c0) = v;
        }
    }
}

// ---------------- prepasses -------------------------------------------------
__global__ __launch_bounds__(256)
void prep_x_kernel(const float* __restrict__ in, __half* __restrict__ out, int n8)
{
    int i = blockIdx.x * 256 + threadIdx.x;
    int stride = gridDim.x * 256;
    for (; i < n8; i += stride) {
        float4 a = ((const float4*)in)[2 * i];
        float4 b = ((const float4*)in)[2 * i + 1];
        __half2 h[4];
        h[0] = __floats2half2_rn(a.x, a.y);
        h[1] = __floats2half2_rn(a.z, a.w);
        h[2] = __floats2half2_rn(b.x, b.y);
        h[3] = __floats2half2_rn(b.z, b.w);
        ((uint4*)out)[i] = *(uint4*)h;
    }
}

__global__ __launch_bounds__(256)
void prep_w_kernel(const float* __restrict__ W, __half* __restrict__ out, int N, int total4)
{
    int i = blockIdx.x * 256 + threadIdx.x;
    int stride = gridDim.x * 256;
    int n4 = N >> 2;
    for (; i < total4; i += stride) {
        int kp = i / n4, j4 = (i - kp * n4) << 2;
        const float* r0 = W + (size_t)(2 * kp) * N + j4;
        const float* r1 = r0 + N;
        float4 a = *(const float4*)r0;
        float4 b = *(const float4*)r1;
        __half2 h[4];
        h[0] = __floats2half2_rn(a.x, b.x);
        h[1] = __floats2half2_rn(a.y, b.y);
        h[2] = __floats2half2_rn(a.z, b.z);
        h[3] = __floats2half2_rn(a.w, b.w);
        ((uint4*)out)[(size_t)kp * n4 + (j4 >> 2)] = *(uint4*)h;
    }
}

// ---------------- RMSNorm + RoPE -> fp16 splits ------------------------------
__global__ __launch_bounds__(256)
void normrope_kernel(const float* __restrict__ qkv, const int* __restrict__ coords,
                     const float* __restrict__ gq, const float* __restrict__ gk,
                     __half* __restrict__ qh, __half* __restrict__ ql,
                     __half* __restrict__ kh, __half* __restrict__ kl,
                     __half* __restrict__ vh)
{
    const int wid  = blockIdx.x * 8 + (threadIdx.x >> 5);
    const int lane = threadIdx.x & 31;
    const int n = wid >> 4;
    const int h = wid & 15;

    const int j = lane;
    float c = 1.f, s = 0.f;
    if (j < 30) {
        int axis = (j >= 20) ? 2 : ((j >= 10) ? 1 : 0);
        int f = j - axis * 10;
        float freq = exp2f((float)f * -1.32877123795494493f);
        float phase = (float)__ldg(coords + n * 3 + axis) * freq;
        sincosf(phase, &s, &c);
    }

    const float* base = qkv + (size_t)n * 3072 + h * 64;
    const size_t oofs = (size_t)n * 1024 + h * 64 + 2 * j;

    auto store_split = [&](float v0, float v1, __half* hi, __half* lo) {
        __half h0 = __float2half_rn(v0);
        __half h1 = __float2half_rn(v1);
        float r0 = v0 - __half2float(h0);
        float r1 = v1 - __half2float(h1);
        __half2 hv; hv.x = h0; hv.y = h1;
        __half2 lv; lv.x = __float2half_rn(r0); lv.y = __float2half_rn(r1);
        *(__half2*)(hi + oofs) = hv;
        *(__half2*)(lo + oofs) = lv;
    };

#pragma unroll
    for (int pass = 0; pass < 2; ++pass) {
        const float* p = base + pass * 1024;
        const float* gamma = (pass == 0 ? gq : gk) + h * 64;
        float2 t = *(const float2*)(p + 2 * j);
        float ss = t.x * t.x + t.y * t.y;
#pragma unroll
        for (int o = 16; o > 0; o >>= 1) ss += __shfl_xor_sync(0xffffffffu, ss, o);
        float inv = 8.0f / fmaxf(sqrtf(ss), 1e-12f);
        float v0 = t.x * inv * __ldg(gamma + 2 * j);
        float v1 = t.y * inv * __ldg(gamma + 2 * j + 1);
        float r0 = v0 * c - v1 * s;
        float r1 = v0 * s + v1 * c;
        if (pass == 0) store_split(r0 * 0.125f, r1 * 0.125f, qh, ql);
        else           store_split(r0, r1, kh, kl);
    }
    {
        float2 t = *(const float2*)(base + 2048 + 2 * j);
        *(__half2*)(vh + oofs) = __floats2half2_rn(t.x, t.y);
    }
}

// ---------------- windowed attention (fp16 HMMA, split-compensated) ---------
// smem: QH 0, QL 18432, 2 KV buffers of (KH, KL, VH) @18432 each
#define AT_QH 0
#define AT_QL 18432
#define AT_KV 36864
#define AT_KVBUF 55296
#define ATTN_SMEM 147456

__device__ __forceinline__ int win_token(int w, int p) {
    int wx = w >> 4, wy = (w >> 2) & 3, wz = w & 3;
    int px = p >> 6, py = (p >> 3) & 7, pz = p & 7;
    return ((((wx << 3) + px) << 10) | (((wy << 3) + py) << 5) | ((wz << 3) + pz));
}

__global__ __launch_bounds__(256, 1)
void attn_kernel(const __half* __restrict__ qh, const __half* __restrict__ ql,
                 const __half* __restrict__ kh, const __half* __restrict__ kl,
                 const __half* __restrict__ vh,
                 __half* __restrict__ hout)
{
    extern __shared__ __align__(16) char smc[];
    const uint32_t sb = (uint32_t)__cvta_generic_to_shared(smc);
    const int tid  = threadIdx.x;
    const int b    = blockIdx.x;
    const int qc   = b & 3;
    const int head = (b >> 2) & 15;
    const int w    = b >> 6;
    const int lane = tid & 31, wid = tid >> 5;
    const int g = lane >> 2, tg = lane & 3;

    auto cp_tile = [&](const __half* src, uint32_t dstB, int pbase) {
#pragma unroll
        for (int i = 0; i < 4; i++) {
            int c = tid + i * 256;
            int r = c >> 3, seg = c & 7;
            int n = win_token(w, pbase + r);
            cpasync16(sb + dstB + (uint32_t)(r * 144 + seg * 16),
                      src + (size_t)n * 1024 + head * 64 + seg * 8);
        }
    };

    cp_tile(qh, AT_QH, qc * 128);
    cp_tile(ql, AT_QL, qc * 128);
    CP_COMMIT();
    cp_tile(kh, AT_KV, 0);
    cp_tile(kl, AT_KV + 18432, 0);
    cp_tile(vh, AT_KV + 36864, 0);
    CP_COMMIT();

    float oacc[8][4];
#pragma unroll
    for (int t = 0; t < 8; t++)
#pragma unroll
        for (int q = 0; q < 4; q++) oacc[t][q] = 0.f;
    float L0 = 0.f, L1 = 0.f;

    const int qrow = wid * 16 + g;
    const uint32_t* qh_g  = (const uint32_t*)(smc + AT_QH) + qrow * 36;
    const uint32_t* qh_g8 = qh_g + 8 * 36;
    const uint32_t* ql_g  = (const uint32_t*)(smc + AT_QL) + qrow * 36;
    const uint32_t* ql_g8 = ql_g + 8 * 36;

    for (int kt = 0; kt < 4; ++kt) {
        if (kt < 3) {
            uint32_t nb = AT_KV + ((kt + 1) & 1) * AT_KVBUF;
            int pb = (kt + 1) * 128;
            cp_tile(kh, nb, pb);
            cp_tile(kl, nb + 18432, pb);
            cp_tile(vh, nb + 36864, pb);
            CP_COMMIT();
            asm volatile("cp.async.wait_group 1;");
        } else {
            asm volatile("cp.async.wait_group 0;");
        }
        __syncthreads();

        const uint32_t kvB = AT_KV + (kt & 1) * AT_KVBUF;
        const uint32_t* KH32 = (const uint32_t*)(smc + kvB);
        const uint32_t* KL32 = (const uint32_t*)(smc + kvB + 18432);
        const uint32_t VHb = sb + kvB + 36864;

#pragma unroll
        for (int nh = 0; nh < 2; ++nh) {
            float sacc[8][4];
#pragma unroll
            for (int t = 0; t < 8; t++)
#pragma unroll
                for (int q = 0; q < 4; q++) sacc[t][q] = 0.f;

#pragma unroll
            for (int ks = 0; ks < 4; ++ks) {
                const int c0 = tg + 8 * ks, c1 = tg + 4 + 8 * ks;
                uint32_t ah[4], al[4];
                ah[0] = qh_g[c0];  ah[1] = qh_g8[c0];
                ah[2] = qh_g[c1];  ah[3] = qh_g8[c1];
                al[0] = ql_g[c0];  al[1] = ql_g8[c0];
                al[2] = ql_g[c1];  al[3] = ql_g8[c1];
#pragma unroll
                for (int ni = 0; ni < 8; ++ni) {
                    const int krow = nh * 64 + ni * 8 + g;
                    const uint32_t* kro = KH32 + krow * 36;
                    uint32_t bh[2] = { kro[c0], kro[c1] };
                    const uint32_t* krl = KL32 + krow * 36;
                    uint32_t bl[2] = { krl[c0], krl[c1] };
                    mma_f16(sacc[ni], ah, bh);
                    mma_f16(sacc[ni], al, bh);
                    mma_f16(sacc[ni], ah, bl);
                }
            }

            uint32_t ph[8][2];
#pragma unroll
            for (int t = 0; t < 8; t++) {
                float e0 = __expf(sacc[t][0]);
                float e1 = __expf(sacc[t][1]);
                float e2 = __expf(sacc[t][2]);
                float e3 = __expf(sacc[t][3]);
                L0 += e0 + e1;
                L1 += e2 + e3;
                ph[t][0] = packh2(e0, e1);
                ph[t][1] = packh2(e2, e3);
            }

#pragma unroll
            for (int k = 0; k < 4; ++k) {
                uint32_t pA[4] = { ph[2 * k][0], ph[2 * k][1], ph[2 * k + 1][0], ph[2 * k + 1][1] };
                const int keybase = nh * 64 + 16 * k;
                const int tl = lane >> 3;
                const uint32_t rowoff = (uint32_t)((keybase + (lane & 7) + (tl & 1) * 8) * 144
                                                  + (tl >> 1) * 16);
#pragma unroll
                for (int c = 0; c < 4; ++c) {
                    uint32_t ad = rowoff + c * 32;
                    uint32_t r0, r1, r2, r3;
                    LDMX4T(r0, r1, r2, r3, VHb + ad);
                    { uint32_t bb[2] = { r0, r1 }; mma_f16(oacc[2 * c], pA, bb); }
                    { uint32_t bb[2] = { r2, r3 }; mma_f16(oacc[2 * c + 1], pA, bb); }
                }
            }
        }
        __syncthreads();
    }

    L0 += __shfl_xor_sync(0xffffffffu, L0, 1);
    L0 += __shfl_xor_sync(0xffffffffu, L0, 2);
    L1 += __shfl_xor_sync(0xffffffffu, L1, 1);
    L1 += __shfl_xor_sync(0xffffffffu, L1, 2);
    const float inv0 = 1.0f / L0;
    const float inv1 = 1.0f / L1;

    const int q0 = qc * 128 + wid * 16 + g;
    const int n0 = win_token(w, q0);
    const int n1 = win_token(w, q0 + 8);
    __half* o0 = hout + (size_t)n0 * 1024 + head * 64 + 2 * tg;
    __half* o1 = hout + (size_t)n1 * 1024 + head * 64 + 2 * tg;
#pragma unroll
    for (int t = 0; t < 8; t++) {
        __half2 h0 = __floats2half2_rn(oacc[t][0] * inv0, oacc[t][1] * inv0);
        __half2 h1 = __floats2half2_rn(oacc[t][2] * inv1, oacc[t][3] * inv1);
        *(__half2*)(o0 + 8 * t) = h0;
        *(__half2*)(o1 + 8 * t) = h1;
    }
}

// ---------------- launch ----------------------------------------------------
extern "C" void kernel_launch(void* const* d_in, const int* in_sizes, int n_in,
                              void* d_out, int out_size)
{
    const float* x      = (const float*)d_in[0];
    const int*   coords = (const int*)d_in[1];
    const float* Wqkv   = (const float*)d_in[2];
    const float* bqkv   = (const float*)d_in[3];
    const float* gq     = (const float*)d_in[4];
    const float* gk     = (const float*)d_in[5];
    const float* Wout   = (const float*)d_in[6];
    const float* bout   = (const float*)d_in[7];
    float* out = (float*)d_out;

    cudaFuncSetAttribute(gemm_f16_kernel, cudaFuncAttributeMaxDynamicSharedMemorySize, GEMM_SMEM);
    cudaFuncSetAttribute(attn_kernel, cudaFuncAttributeMaxDynamicSharedMemorySize, ATTN_SMEM);

    float* qkv_ptr;
    __half *h16, *x16, *w1p, *w2p, *pqh, *pql, *pkh, *pkl, *pvh;
    cudaGetSymbolAddress((void**)&qkv_ptr, g_qkv);
    cudaGetSymbolAddress((void**)&h16, g_h16);
    cudaGetSymbolAddress((void**)&x16, g_x16);
    cudaGetSymbolAddress((void**)&w1p, g_w1p);
    cudaGetSymbolAddress((void**)&w2p, g_w2p);
    cudaGetSymbolAddress((void**)&pqh, g_qh);
    cudaGetSymbolAddress((void**)&pql, g_ql);
    cudaGetSymbolAddress((void**)&pkh, g_kh);
    cudaGetSymbolAddress((void**)&pkl, g_kl);
    cudaGetSymbolAddress((void**)&pvh, g_vh);

    // prepasses
    prep_x_kernel<<<4096, 256>>>(x, x16, NTOK * CDIM / 8);
    prep_w_kernel<<<4096, 256>>>(Wqkv, w1p, 3 * CDIM, (CDIM / 2) * (3 * CDIM) / 4);
    prep_w_kernel<<<2048, 256>>>(Wout, w2p, CDIM, (CDIM / 2) * CDIM / 4);

    // 1) qkv = x @ Wqkv + bqkv
    gemm_f16_kernel<<<dim3(3072 / 128, NTOK / 128), 256, GEMM_SMEM>>>(
        x16, w1p, bqkv, qkv_ptr, NTOK, 3072, CDIM);

    // 2) RMSNorm + RoPE -> fp16 splits
    normrope_kernel<<<(NTOK * NHEAD) / 8, 256>>>(qkv_ptr, coords, gq, gk,
                                                 pqh, pql, pkh, pkl, pvh);

    // 3) windowed attention (fp16 HMMA) -> h fp16
    attn_kernel<<<64 * 16 * 4, 256, ATTN_SMEM>>>(pqh, pql, pkh, pkl, pvh, h16);

    // 4) out = h @ Wout + bout
    gemm_f16_kernel<<<dim3(1024 / 128, NTOK / 128), 256, GEMM_SMEM>>>(
        h16, w2p, bout, out, NTOK, 1024, CDIM);
}